// round 8
// baseline (speedup 1.0000x reference)
#include <cuda_runtime.h>
#include <math.h>
#include <stdint.h>

#define B_  8
#define Q_  512
#define D_  4096
#define H_  1024

#define STAGES  3
#define TILE    128
#define BK      32
#define STRD    36                        // K-major smem row stride (floats)
#define STRD_BN 136                       // NN B smem row stride (floats; mod 32 == 8 -> conflict-free)
#define A_FLOATS (TILE * STRD)            // 4608
#define B_FLOATS (TILE * STRD)            // 4608 (NN needs 32*136=4352 <= this)
#define STAGE_FLOATS (A_FLOATS + B_FLOATS)      // 9216
#define SMEM_BYTES (STAGES * STAGE_FLOATS * 4)  // 110592

// ---------------- scratch (static device memory; no allocs allowed) ----------
__device__ float g_q[(size_t)B_ * Q_ * H_];       // projected queries, tf32
__device__ float g_doc[(size_t)B_ * D_ * H_];     // tf32(doc)
__device__ float g_W[(size_t)H_ * H_];            // tf32(W)
__device__ float g_part[(size_t)B_ * Q_ * H_];    // split-K partial for GEMM3

// ---------------- helpers -----------------------------------------------------
__device__ __forceinline__ float tf32_rn(float x) {
    float r; asm("cvt.rna.tf32.f32 %0, %1;" : "=f"(r) : "f"(x)); return r;
}
__device__ __forceinline__ uint32_t tf32u(float x) {
    float r; asm("cvt.rna.tf32.f32 %0, %1;" : "=f"(r) : "f"(x));
    return __float_as_uint(r);
}
__device__ __forceinline__ void cp_async16(uint32_t dst, const void* src) {
    asm volatile("cp.async.cg.shared.global [%0], [%1], 16;" :: "r"(dst), "l"(src));
}
#define CP_COMMIT() asm volatile("cp.async.commit_group;" ::: "memory")
#define CP_WAIT(n)  asm volatile("cp.async.wait_group %0;" :: "n"(n) : "memory")

__device__ __forceinline__ uint32_t smem_u32(const void* p) {
    uint32_t a;
    asm("{ .reg .u64 t; cvta.to.shared.u64 t, %1; cvt.u32.u64 %0, t; }" : "=r"(a) : "l"(p));
    return a;
}

__device__ __forceinline__ void mma_tf32(float* c, const uint32_t* a, const uint32_t* b) {
    asm volatile(
        "mma.sync.aligned.m16n8k8.row.col.f32.tf32.tf32.f32 "
        "{%0,%1,%2,%3}, {%4,%5,%6,%7}, {%8,%9}, {%0,%1,%2,%3};"
        : "+f"(c[0]), "+f"(c[1]), "+f"(c[2]), "+f"(c[3])
        : "r"(a[0]), "r"(a[1]), "r"(a[2]), "r"(a[3]), "r"(b[0]), "r"(b[1]));
}

// ---------------- warp-MMA TF32 GEMM (CTA 128x128, warp 32x64, BK=32) ---------
// C[m][n] = alpha * sum_k A[m][k] * op(B) (+ bias[n])
//   A: [M,K] K-major, pitch lda (fp32; CVT_A => round in-register)
//   B_KMAJOR=1: B is [N,K] K-major rows, pitch ldb (pre-rounded tf32)
//   B_KMAJOR=0: B is [K,N], pitch ldb (pre-rounded tf32)
// Split-K: grid.z = batches * nsplit; split s handles K-range [s*K/nsplit, ...)
// and writes to C + s*splitStrideC.
// grid: (N/128, M/128, batches*nsplit), 256 threads, 2 CTAs/SM.
template <bool B_KMAJOR, bool HAS_BIAS, bool CVT_A, bool CVT_OUT>
__global__ void __launch_bounds__(256, 2) wgemm(
    const float* __restrict__ A, const float* __restrict__ Bm,
    float* __restrict__ C, const float* __restrict__ bias,
    int K, int lda, int ldb, int ldc, float alpha,
    size_t strideA, size_t strideB, size_t strideC,
    int nsplit, size_t splitStrideC)
{
    extern __shared__ float smf[];
    const uint32_t sbase = smem_u32(smf);

    const int tid  = threadIdx.x;
    const int lane = tid & 31;
    const int wid  = tid >> 5;
    const int row  = lane >> 2;          // 0..7
    const int tig  = lane & 3;           // 0..3
    const int warp_m = (wid & 3) * 32;   // 4 warps in M
    const int warp_n = (wid >> 2) * 64;  // 2 warps in N

    const int Kc = K / nsplit;
    const size_t batch = blockIdx.z / nsplit;
    const int    sp    = blockIdx.z % nsplit;

    const float* Ab = A + batch * strideA + (size_t)(blockIdx.y * TILE) * lda
                        + (size_t)sp * Kc;
    const float* Bb;
    if (B_KMAJOR)
        Bb = Bm + batch * strideB + (size_t)(blockIdx.x * TILE) * ldb + (size_t)sp * Kc;
    else
        Bb = Bm + batch * strideB + blockIdx.x * TILE + (size_t)sp * Kc * ldb;

    float acc[2][8][4];
#pragma unroll
    for (int mt = 0; mt < 2; mt++)
#pragma unroll
        for (int nt = 0; nt < 8; nt++)
#pragma unroll
            for (int i = 0; i < 4; i++) acc[mt][nt][i] = 0.0f;

    const int NK = Kc / BK;

    auto load_stage = [&](int kb) {
        const int s = kb % STAGES;
        const uint32_t stA = sbase + s * STAGE_FLOATS * 4;
        const uint32_t stB = stA + A_FLOATS * 4;
        const float* gA = Ab + kb * BK;
#pragma unroll
        for (int r = 0; r < 4; r++) {
            const int c = tid + r * 256;          // 0..1023
            const int ar = c >> 3, aq = (c & 7) * 4;
            cp_async16(stA + (ar * STRD + aq) * 4, gA + (size_t)ar * lda + aq);
        }
        if (B_KMAJOR) {
            const float* gB = Bb + kb * BK;
#pragma unroll
            for (int r = 0; r < 4; r++) {
                const int c = tid + r * 256;
                const int br = c >> 3, bq = (c & 7) * 4;
                cp_async16(stB + (br * STRD + bq) * 4, gB + (size_t)br * ldb + bq);
            }
        } else {
            const float* gB = Bb + (size_t)(kb * BK) * ldb;
#pragma unroll
            for (int r = 0; r < 4; r++) {
                const int c = tid + r * 256;      // 0..1023
                const int bk = c >> 5, bn = (c & 31) * 4;
                cp_async16(stB + (bk * STRD_BN + bn) * 4, gB + (size_t)bk * ldb + bn);
            }
        }
    };

#pragma unroll
    for (int s = 0; s < STAGES - 1; s++) {
        load_stage(s);
        CP_COMMIT();
    }

    for (int kb = 0; kb < NK; kb++) {
        CP_WAIT(STAGES - 2);
        __syncthreads();

        const int kn = kb + STAGES - 1;
        if (kn < NK) load_stage(kn);
        CP_COMMIT();

        const float* As = smf + (kb % STAGES) * STAGE_FLOATS;
        const float* Bs = As + A_FLOATS;
#pragma unroll
        for (int kk = 0; kk < BK; kk += 8) {
            uint32_t a[2][4], b[8][2];
#pragma unroll
            for (int mt = 0; mt < 2; mt++) {
                const float* ap = As + (warp_m + mt * 16 + row) * STRD + kk + tig;
                if (CVT_A) {
                    a[mt][0] = tf32u(ap[0]);
                    a[mt][1] = tf32u(ap[8 * STRD]);
                    a[mt][2] = tf32u(ap[4]);
                    a[mt][3] = tf32u(ap[8 * STRD + 4]);
                } else {
                    a[mt][0] = __float_as_uint(ap[0]);
                    a[mt][1] = __float_as_uint(ap[8 * STRD]);
                    a[mt][2] = __float_as_uint(ap[4]);
                    a[mt][3] = __float_as_uint(ap[8 * STRD + 4]);
                }
            }
#pragma unroll
            for (int nt = 0; nt < 8; nt++) {
                if (B_KMAJOR) {
                    const float* bp = Bs + (warp_n + nt * 8 + row) * STRD + kk + tig;
                    b[nt][0] = __float_as_uint(bp[0]);
                    b[nt][1] = __float_as_uint(bp[4]);
                } else {
                    const float* bp = Bs + (size_t)(kk + tig) * STRD_BN + warp_n + nt * 8 + row;
                    b[nt][0] = __float_as_uint(bp[0]);
                    b[nt][1] = __float_as_uint(bp[4 * STRD_BN]);
                }
            }
#pragma unroll
            for (int mt = 0; mt < 2; mt++)
#pragma unroll
                for (int nt = 0; nt < 8; nt++)
                    mma_tf32(acc[mt][nt], a[mt], b[nt]);
        }
        __syncthreads();
    }

    // ---- epilogue ----
    float* Cb = C + batch * strideC + (size_t)sp * splitStrideC;
#pragma unroll
    for (int mt = 0; mt < 2; mt++) {
        const int r0 = blockIdx.y * TILE + warp_m + mt * 16 + row;
#pragma unroll
        for (int nt = 0; nt < 8; nt++) {
            const int col = blockIdx.x * TILE + warp_n + nt * 8 + 2 * tig;
            float bx = 0.f, by = 0.f;
            if (HAS_BIAS) { bx = __ldg(bias + col); by = __ldg(bias + col + 1); }
            float2 v0, v1;
            v0.x = acc[mt][nt][0] * alpha + bx;
            v0.y = acc[mt][nt][1] * alpha + by;
            v1.x = acc[mt][nt][2] * alpha + bx;
            v1.y = acc[mt][nt][3] * alpha + by;
            if (CVT_OUT) {
                v0.x = tf32_rn(v0.x); v0.y = tf32_rn(v0.y);
                v1.x = tf32_rn(v1.x); v1.y = tf32_rn(v1.y);
            }
            *(float2*)(Cb + (size_t)r0 * ldc + col) = v0;
            *(float2*)(Cb + (size_t)(r0 + 8) * ldc + col) = v1;
        }
    }
}

// ---------------- elementwise tf32 round copy ---------------------------------
__global__ void k_cvt(const float* __restrict__ src, float* __restrict__ dst) {
    size_t i = (size_t)blockIdx.x * blockDim.x + threadIdx.x;
    float4 v = ((const float4*)src)[i];
    v.x = tf32_rn(v.x); v.y = tf32_rn(v.y); v.z = tf32_rn(v.z); v.w = tf32_rn(v.w);
    ((float4*)dst)[i] = v;
}

// ---------------- split-K reduction: dst += src --------------------------------
__global__ void k_add(float* __restrict__ dst, const float* __restrict__ src) {
    size_t i = (size_t)blockIdx.x * blockDim.x + threadIdx.x;
    float4 a = ((const float4*)dst)[i];
    float4 b = ((const float4*)src)[i];
    a.x += b.x; a.y += b.y; a.z += b.z; a.w += b.w;
    ((float4*)dst)[i] = a;
}

// ---------------- masked softmax over D (in place, tf32-rounded output) -------
__global__ void __launch_bounds__(256) softmax_kernel(
    float* __restrict__ attn, const int* __restrict__ mask)
{
    const int row = blockIdx.x;            // b*Q_ + q
    const int b = row / Q_;
    const int4* mrow = (const int4*)(mask + (size_t)b * D_);
    float4* s4 = (float4*)(attn + (size_t)row * D_);
    const int tid = threadIdx.x;

    float v[16];
    float mx = -INFINITY;
#pragma unroll
    for (int i = 0; i < 4; i++) {
        const int c = tid + i * 256;
        int4 m = mrow[c];
        float4 x = s4[c];
        v[i * 4 + 0] = (m.x != 0) ? x.x : -INFINITY;
        v[i * 4 + 1] = (m.y != 0) ? x.y : -INFINITY;
        v[i * 4 + 2] = (m.z != 0) ? x.z : -INFINITY;
        v[i * 4 + 3] = (m.w != 0) ? x.w : -INFINITY;
        mx = fmaxf(mx, fmaxf(fmaxf(v[i * 4], v[i * 4 + 1]), fmaxf(v[i * 4 + 2], v[i * 4 + 3])));
    }

    __shared__ float red[8];
#pragma unroll
    for (int off = 16; off > 0; off >>= 1)
        mx = fmaxf(mx, __shfl_xor_sync(0xffffffffu, mx, off));
    if ((tid & 31) == 0) red[tid >> 5] = mx;
    __syncthreads();
    if (tid < 32) {
        float m2 = (tid < 8) ? red[tid] : -INFINITY;
#pragma unroll
        for (int off = 4; off > 0; off >>= 1)
            m2 = fmaxf(m2, __shfl_xor_sync(0xffffffffu, m2, off));
        if (tid == 0) red[0] = m2;
    }
    __syncthreads();
    mx = red[0];

    float sum = 0.0f;
#pragma unroll
    for (int i = 0; i < 16; i++) {
        float e = (v[i] != -INFINITY) ? expf(v[i] - mx) : 0.0f;
        v[i] = e;
        sum += e;
    }
#pragma unroll
    for (int off = 16; off > 0; off >>= 1)
        sum += __shfl_xor_sync(0xffffffffu, sum, off);
    __syncthreads();
    if ((tid & 31) == 0) red[tid >> 5] = sum;
    __syncthreads();
    if (tid < 32) {
        float s2 = (tid < 8) ? red[tid] : 0.0f;
#pragma unroll
        for (int off = 4; off > 0; off >>= 1)
            s2 += __shfl_xor_sync(0xffffffffu, s2, off);
        if (tid == 0) red[0] = s2;
    }
    __syncthreads();
    const float inv = 1.0f / red[0];

    // write tf32-rounded weights: both the kernel output and GEMM3's A operand
#pragma unroll
    for (int i = 0; i < 4; i++) {
        float4 o;
        o.x = tf32_rn(v[i * 4 + 0] * inv);
        o.y = tf32_rn(v[i * 4 + 1] * inv);
        o.z = tf32_rn(v[i * 4 + 2] * inv);
        o.w = tf32_rn(v[i * 4 + 3] * inv);
        s4[tid + i * 256] = o;
    }
}

// ---------------- launch --------------------------------------------------------
extern "C" void kernel_launch(void* const* d_in, const int* in_sizes, int n_in,
                              void* d_out, int out_size)
{
    const float* query = (const float*)d_in[0];   // [B,Q,H]
    const float* doc   = (const float*)d_in[1];   // [B,D,H]
    const int*   mask  = (const int*)d_in[2];     // [B,D]
    const float* W     = (const float*)d_in[3];   // [H,H]
    const float* bias  = (const float*)d_in[4];   // [H]

    float* out = (float*)d_out;
    float* retrieved = out;                               // [B,Q,H]
    float* attn = out + (size_t)B_ * Q_ * H_;             // [B,Q,D]

    float *p_q, *p_doc, *p_W, *p_part;
    cudaGetSymbolAddress((void**)&p_q, g_q);
    cudaGetSymbolAddress((void**)&p_doc, g_doc);
    cudaGetSymbolAddress((void**)&p_W, g_W);
    cudaGetSymbolAddress((void**)&p_part, g_part);

    cudaFuncSetAttribute(wgemm<false, true, true, true>,
                         cudaFuncAttributeMaxDynamicSharedMemorySize, SMEM_BYTES);
    cudaFuncSetAttribute(wgemm<true, false, false, false>,
                         cudaFuncAttributeMaxDynamicSharedMemorySize, SMEM_BYTES);
    cudaFuncSetAttribute(wgemm<false, false, false, false>,
                         cudaFuncAttributeMaxDynamicSharedMemorySize, SMEM_BYTES);

    // prep: pre-round doc and W to tf32
    k_cvt<<<((size_t)B_ * D_ * H_) / 4 / 256, 256>>>(doc, p_doc);
    k_cvt<<<((size_t)H_ * H_) / 4 / 256, 256>>>(W, p_W);

    const float scale = 1.0f / 32.0f;   // 1/sqrt(H)

    // 1) q = query @ W + bias  (M=4096, N=1024, K=1024); B = g_W [K,N] NN
    {
        dim3 g(H_ / TILE, (B_ * Q_) / TILE, 1);
        wgemm<false, true, true, true><<<g, 256, SMEM_BYTES>>>(
            query, p_W, p_q, bias, H_, H_, H_, H_, 1.0f, 0, 0, 0, 1, 0);
    }
    // 2) scores = q @ doc^T * scale -> attn; B = g_doc [N,K] NT
    {
        dim3 g(D_ / TILE, Q_ / TILE, B_);
        wgemm<true, false, false, false><<<g, 256, SMEM_BYTES>>>(
            p_q, p_doc, attn, nullptr, H_, H_, H_, D_, scale,
            (size_t)Q_ * H_, (size_t)D_ * H_, (size_t)Q_ * D_, 1, 0);
    }
    // 3) masked softmax in place over D (emits tf32-rounded weights)
    softmax_kernel<<<B_ * Q_, 256>>>(attn, mask);
    // 4) retrieved = attn @ doc; B = g_doc [K,N] NN, K = D, split-K = 2
    //    split 0 -> retrieved, split 1 -> g_part; then retrieved += g_part
    {
        const size_t splitStride = (size_t)(p_part - retrieved);
        dim3 g(H_ / TILE, Q_ / TILE, B_ * 2);
        wgemm<false, false, false, false><<<g, 256, SMEM_BYTES>>>(
            attn, p_doc, retrieved, nullptr, D_, D_, H_, H_, 1.0f,
            (size_t)Q_ * D_, (size_t)D_ * H_, (size_t)Q_ * H_, 2, splitStride);
        k_add<<<((size_t)B_ * Q_ * H_) / 4 / 256, 256>>>(retrieved, p_part);
    }
}

// round 9
// speedup vs baseline: 1.5130x; 1.5130x over previous
#include <cuda_runtime.h>
#include <cuda_fp16.h>
#include <math.h>
#include <stdint.h>

#define B_  8
#define Q_  512
#define D_  4096
#define H_  1024

#define STAGES  4
#define TILE    128
#define BK      32                         // k elements (halves) per stage
#define STRD_H  40                         // smem row stride in halves (bank-safe)
#define A_HALVES (TILE * STRD_H)           // 5120
#define STAGE_HALVES (2 * A_HALVES)        // 10240
#define SMEM_BYTES (STAGES * STAGE_HALVES * 2)   // 81920

// ---------------- scratch (static device memory; no allocs allowed) ----------
__device__ __align__(16) __half g_q16[(size_t)B_ * Q_ * H_];     // projected queries
__device__ __align__(16) __half g_query16[(size_t)B_ * Q_ * H_]; // fp16(query)
__device__ __align__(16) __half g_WT16[(size_t)H_ * H_];         // fp16(W^T) [n][k]
__device__ __align__(16) __half g_doc16[(size_t)B_ * D_ * H_];   // fp16(doc)  [B,D,H]
__device__ __align__(16) __half g_docT16[(size_t)B_ * H_ * D_];  // fp16(doc^T)[B,H,D]
__device__ __align__(16) __half g_attn16[(size_t)B_ * Q_ * D_];  // fp16(attn) [B,Q,D]

// ---------------- helpers -----------------------------------------------------
__device__ __forceinline__ void cp_async16(uint32_t dst, const void* src) {
    asm volatile("cp.async.cg.shared.global [%0], [%1], 16;" :: "r"(dst), "l"(src));
}
#define CP_COMMIT() asm volatile("cp.async.commit_group;" ::: "memory")
#define CP_WAIT(n)  asm volatile("cp.async.wait_group %0;" :: "n"(n) : "memory")

__device__ __forceinline__ uint32_t smem_u32(const void* p) {
    uint32_t a;
    asm("{ .reg .u64 t; cvta.to.shared.u64 t, %1; cvt.u32.u64 %0, t; }" : "=r"(a) : "l"(p));
    return a;
}

__device__ __forceinline__ void mma_f16(float* c, const uint32_t* a, const uint32_t* b) {
    asm volatile(
        "mma.sync.aligned.m16n8k16.row.col.f32.f16.f16.f32 "
        "{%0,%1,%2,%3}, {%4,%5,%6,%7}, {%8,%9}, {%0,%1,%2,%3};"
        : "+f"(c[0]), "+f"(c[1]), "+f"(c[2]), "+f"(c[3])
        : "r"(a[0]), "r"(a[1]), "r"(a[2]), "r"(a[3]), "r"(b[0]), "r"(b[1]));
}

// ---------------- warp-MMA FP16 GEMM (CTA 128x128, warp 32x64, BK=32) ---------
// C[m][n] = alpha * sum_k A[m][k] * B[n][k] (+ bias[n])
// A: [M,K] K-major fp16, pitch lda (halves). B: [N,K] K-major fp16, pitch ldb.
// OUT_HALF: C is fp16 (pitch ldc halves); else fp32.
// grid: (N/128, M/128, batches), 256 threads, 2 CTAs/SM.
template <bool HAS_BIAS, bool OUT_HALF>
__global__ void __launch_bounds__(256, 2) wgemm_h(
    const __half* __restrict__ A, const __half* __restrict__ Bm,
    void* __restrict__ Cv, const float* __restrict__ bias,
    int K, int lda, int ldb, int ldc, float alpha,
    size_t strideA, size_t strideB, size_t strideC)
{
    extern __shared__ __half smh[];
    const uint32_t sbase = smem_u32(smh);

    const int tid  = threadIdx.x;
    const int lane = tid & 31;
    const int wid  = tid >> 5;
    const int gid  = lane >> 2;          // 0..7
    const int tig  = lane & 3;           // 0..3
    const int warp_m = (wid & 3) * 32;   // 4 warps in M
    const int warp_n = (wid >> 2) * 64;  // 2 warps in N

    const size_t batch = blockIdx.z;
    const __half* Ab = A + batch * strideA + (size_t)(blockIdx.y * TILE) * lda;
    const __half* Bb = Bm + batch * strideB + (size_t)(blockIdx.x * TILE) * ldb;

    float acc[2][8][4];
#pragma unroll
    for (int mt = 0; mt < 2; mt++)
#pragma unroll
        for (int nt = 0; nt < 8; nt++)
#pragma unroll
            for (int i = 0; i < 4; i++) acc[mt][nt][i] = 0.0f;

    const int NK = K / BK;

    auto load_stage = [&](int kb) {
        const int s = kb % STAGES;
        const uint32_t stA = sbase + s * STAGE_HALVES * 2;
        const uint32_t stB = stA + A_HALVES * 2;
        const __half* gA = Ab + kb * BK;
        const __half* gB = Bb + kb * BK;
#pragma unroll
        for (int r = 0; r < 2; r++) {
            const int c = tid + r * 256;          // 0..511 chunks
            const int rw = c >> 2, q = (c & 3) * 8;   // q in halves (16B chunks)
            cp_async16(stA + (rw * STRD_H + q) * 2, gA + (size_t)rw * lda + q);
        }
#pragma unroll
        for (int r = 0; r < 2; r++) {
            const int c = tid + r * 256;
            const int rw = c >> 2, q = (c & 3) * 8;
            cp_async16(stB + (rw * STRD_H + q) * 2, gB + (size_t)rw * ldb + q);
        }
    };

#pragma unroll
    for (int s = 0; s < STAGES - 1; s++) {
        load_stage(s);
        CP_COMMIT();
    }

    for (int kb = 0; kb < NK; kb++) {
        CP_WAIT(STAGES - 2);
        __syncthreads();

        const int kn = kb + STAGES - 1;
        if (kn < NK) load_stage(kn);
        CP_COMMIT();

        const __half* As = smh + (kb % STAGES) * STAGE_HALVES;
        const __half* Bs = As + A_HALVES;
#pragma unroll
        for (int kk = 0; kk < BK; kk += 16) {
            uint32_t a[2][4], b[8][2];
#pragma unroll
            for (int mt = 0; mt < 2; mt++) {
                const __half* ap = As + (warp_m + mt * 16 + gid) * STRD_H + kk + 2 * tig;
                a[mt][0] = *(const uint32_t*)ap;
                a[mt][1] = *(const uint32_t*)(ap + 8 * STRD_H);
                a[mt][2] = *(const uint32_t*)(ap + 8);
                a[mt][3] = *(const uint32_t*)(ap + 8 * STRD_H + 8);
            }
#pragma unroll
            for (int nt = 0; nt < 8; nt++) {
                const __half* bp = Bs + (warp_n + nt * 8 + gid) * STRD_H + kk + 2 * tig;
                b[nt][0] = *(const uint32_t*)bp;
                b[nt][1] = *(const uint32_t*)(bp + 8);
            }
#pragma unroll
            for (int mt = 0; mt < 2; mt++)
#pragma unroll
                for (int nt = 0; nt < 8; nt++)
                    mma_f16(acc[mt][nt], a[mt], b[nt]);
        }
        __syncthreads();
    }

    // ---- epilogue ----
#pragma unroll
    for (int mt = 0; mt < 2; mt++) {
        const int r0 = blockIdx.y * TILE + warp_m + mt * 16 + gid;
#pragma unroll
        for (int nt = 0; nt < 8; nt++) {
            const int col = blockIdx.x * TILE + warp_n + nt * 8 + 2 * tig;
            float bx = 0.f, by = 0.f;
            if (HAS_BIAS) { bx = __ldg(bias + col); by = __ldg(bias + col + 1); }
            float2 v0, v1;
            v0.x = acc[mt][nt][0] * alpha + bx;
            v0.y = acc[mt][nt][1] * alpha + by;
            v1.x = acc[mt][nt][2] * alpha + bx;
            v1.y = acc[mt][nt][3] * alpha + by;
            if (OUT_HALF) {
                __half* Cb = (__half*)Cv + batch * strideC;
                *(__half2*)(Cb + (size_t)r0 * ldc + col) =
                    __floats2half2_rn(v0.x, v0.y);
                *(__half2*)(Cb + (size_t)(r0 + 8) * ldc + col) =
                    __floats2half2_rn(v1.x, v1.y);
            } else {
                float* Cb = (float*)Cv + batch * strideC;
                *(float2*)(Cb + (size_t)r0 * ldc + col) = v0;
                *(float2*)(Cb + (size_t)(r0 + 8) * ldc + col) = v1;
            }
        }
    }
}

// ---------------- prep: flat fp32 -> fp16 --------------------------------------
__global__ void k_cvt_h(const float* __restrict__ src, __half* __restrict__ dst) {
    size_t i = (size_t)blockIdx.x * blockDim.x + threadIdx.x;
    float4 v = ((const float4*)src)[i];
    __half2 lo = __floats2half2_rn(v.x, v.y);
    __half2 hi = __floats2half2_rn(v.z, v.w);
    ((__half2*)dst)[i * 2]     = lo;
    ((__half2*)dst)[i * 2 + 1] = hi;
}

// ---------------- prep: W [K,N] -> WT fp16 [N,K] --------------------------------
__global__ void k_prep_W(const float* __restrict__ W, __half* __restrict__ WT) {
    __shared__ __half t[32][33];
    const int bx = blockIdx.x * 32;   // n
    const int by = blockIdx.y * 32;   // k
    const int x = threadIdx.x, y = threadIdx.y;
#pragma unroll
    for (int r = 0; r < 4; r++)
        t[y + 8 * r][x] = __float2half_rn(W[(size_t)(by + y + 8 * r) * H_ + bx + x]);
    __syncthreads();
#pragma unroll
    for (int r = 0; r < 4; r++)
        WT[(size_t)(bx + y + 8 * r) * H_ + by + x] = t[x][y + 8 * r];
}

// ---------------- prep: doc -> doc16 [B,D,H] + docT16 [B,H,D] -------------------
__global__ void k_prep_doc(const float* __restrict__ doc,
                           __half* __restrict__ doc16,
                           __half* __restrict__ docT16) {
    __shared__ __half t[32][33];
    const size_t b = blockIdx.z;
    const float* Db = doc + b * (size_t)D_ * H_;
    __half* Gd = doc16 + b * (size_t)D_ * H_;
    __half* Gt = docT16 + b * (size_t)H_ * D_;
    const int bx = blockIdx.x * 32;   // h
    const int by = blockIdx.y * 32;   // d
    const int x = threadIdx.x, y = threadIdx.y;
#pragma unroll
    for (int r = 0; r < 4; r++) {
        int rw = y + 8 * r;
        __half v = __float2half_rn(Db[(size_t)(by + rw) * H_ + bx + x]);
        Gd[(size_t)(by + rw) * H_ + bx + x] = v;
        t[rw][x] = v;
    }
    __syncthreads();
#pragma unroll
    for (int r = 0; r < 4; r++)
        Gt[(size_t)(bx + y + 8 * r) * D_ + by + x] = t[x][y + 8 * r];
}

// ---------------- masked softmax over D: fp32 out (in place) + fp16 copy -------
__global__ void __launch_bounds__(256) softmax_kernel(
    float* __restrict__ attn, const int* __restrict__ mask,
    __half* __restrict__ attn16)
{
    const int row = blockIdx.x;            // b*Q_ + q
    const int b = row / Q_;
    const int4* mrow = (const int4*)(mask + (size_t)b * D_);
    float4* s4 = (float4*)(attn + (size_t)row * D_);
    __half2* h2 = (__half2*)(attn16 + (size_t)row * D_);
    const int tid = threadIdx.x;

    float v[16];
    float mx = -INFINITY;
#pragma unroll
    for (int i = 0; i < 4; i++) {
        const int c = tid + i * 256;
        int4 m = mrow[c];
        float4 x = s4[c];
        v[i * 4 + 0] = (m.x != 0) ? x.x : -INFINITY;
        v[i * 4 + 1] = (m.y != 0) ? x.y : -INFINITY;
        v[i * 4 + 2] = (m.z != 0) ? x.z : -INFINITY;
        v[i * 4 + 3] = (m.w != 0) ? x.w : -INFINITY;
        mx = fmaxf(mx, fmaxf(fmaxf(v[i * 4], v[i * 4 + 1]), fmaxf(v[i * 4 + 2], v[i * 4 + 3])));
    }

    __shared__ float red[8];
#pragma unroll
    for (int off = 16; off > 0; off >>= 1)
        mx = fmaxf(mx, __shfl_xor_sync(0xffffffffu, mx, off));
    if ((tid & 31) == 0) red[tid >> 5] = mx;
    __syncthreads();
    if (tid < 32) {
        float m2 = (tid < 8) ? red[tid] : -INFINITY;
#pragma unroll
        for (int off = 4; off > 0; off >>= 1)
            m2 = fmaxf(m2, __shfl_xor_sync(0xffffffffu, m2, off));
        if (tid == 0) red[0] = m2;
    }
    __syncthreads();
    mx = red[0];

    float sum = 0.0f;
#pragma unroll
    for (int i = 0; i < 16; i++) {
        float e = (v[i] != -INFINITY) ? expf(v[i] - mx) : 0.0f;
        v[i] = e;
        sum += e;
    }
#pragma unroll
    for (int off = 16; off > 0; off >>= 1)
        sum += __shfl_xor_sync(0xffffffffu, sum, off);
    __syncthreads();
    if ((tid & 31) == 0) red[tid >> 5] = sum;
    __syncthreads();
    if (tid < 32) {
        float s2 = (tid < 8) ? red[tid] : 0.0f;
#pragma unroll
        for (int off = 4; off > 0; off >>= 1)
            s2 += __shfl_xor_sync(0xffffffffu, s2, off);
        if (tid == 0) red[0] = s2;
    }
    __syncthreads();
    const float inv = 1.0f / red[0];

#pragma unroll
    for (int i = 0; i < 4; i++) {
        const int c = tid + i * 256;
        float4 o;
        o.x = v[i * 4 + 0] * inv;
        o.y = v[i * 4 + 1] * inv;
        o.z = v[i * 4 + 2] * inv;
        o.w = v[i * 4 + 3] * inv;
        s4[c] = o;                                   // fp32 output
        h2[c * 2]     = __floats2half2_rn(o.x, o.y); // fp16 operand for GEMM3
        h2[c * 2 + 1] = __floats2half2_rn(o.z, o.w);
    }
}

// ---------------- launch --------------------------------------------------------
extern "C" void kernel_launch(void* const* d_in, const int* in_sizes, int n_in,
                              void* d_out, int out_size)
{
    const float* query = (const float*)d_in[0];   // [B,Q,H]
    const float* doc   = (const float*)d_in[1];   // [B,D,H]
    const int*   mask  = (const int*)d_in[2];     // [B,D]
    const float* W     = (const float*)d_in[3];   // [H,H]
    const float* bias  = (const float*)d_in[4];   // [H]

    float* out = (float*)d_out;
    float* retrieved = out;                               // [B,Q,H]
    float* attn = out + (size_t)B_ * Q_ * H_;             // [B,Q,D]

    __half *p_q16, *p_query16, *p_WT16, *p_doc16, *p_docT16, *p_attn16;
    cudaGetSymbolAddress((void**)&p_q16, g_q16);
    cudaGetSymbolAddress((void**)&p_query16, g_query16);
    cudaGetSymbolAddress((void**)&p_WT16, g_WT16);
    cudaGetSymbolAddress((void**)&p_doc16, g_doc16);
    cudaGetSymbolAddress((void**)&p_docT16, g_docT16);
    cudaGetSymbolAddress((void**)&p_attn16, g_attn16);

    cudaFuncSetAttribute(wgemm_h<true, true>,
                         cudaFuncAttributeMaxDynamicSharedMemorySize, SMEM_BYTES);
    cudaFuncSetAttribute(wgemm_h<false, false>,
                         cudaFuncAttributeMaxDynamicSharedMemorySize, SMEM_BYTES);

    // prep: fp16 conversions (+ transposes)
    k_cvt_h<<<((size_t)B_ * Q_ * H_) / 4 / 256, 256>>>(query, p_query16);
    {
        dim3 g(H_ / 32, H_ / 32, 1);
        k_prep_W<<<g, dim3(32, 8)>>>(W, p_WT16);
    }
    {
        dim3 g(H_ / 32, D_ / 32, B_);
        k_prep_doc<<<g, dim3(32, 8)>>>(doc, p_doc16, p_docT16);
    }

    const float scale = 1.0f / 32.0f;   // 1/sqrt(H)

    // 1) q = query @ W + bias  (M=4096, N=1024, K=1024); B = WT16 [n][k]
    {
        dim3 g(H_ / TILE, (B_ * Q_) / TILE, 1);
        wgemm_h<true, true><<<g, 256, SMEM_BYTES>>>(
            p_query16, p_WT16, p_q16, bias, H_, H_, H_, H_, 1.0f, 0, 0, 0);
    }
    // 2) scores = q @ doc^T * scale -> attn fp32; B = doc16 [d][h]
    {
        dim3 g(D_ / TILE, Q_ / TILE, B_);
        wgemm_h<false, false><<<g, 256, SMEM_BYTES>>>(
            p_q16, p_doc16, attn, nullptr, H_, H_, H_, D_, scale,
            (size_t)Q_ * H_, (size_t)D_ * H_, (size_t)Q_ * D_);
    }
    // 3) masked softmax: fp32 weights (output) + fp16 operand copy
    softmax_kernel<<<B_ * Q_, 256>>>(attn, mask, p_attn16);
    // 4) retrieved = attn @ doc; B = docT16 [h][d], K = D
    {
        dim3 g(H_ / TILE, Q_ / TILE, B_);
        wgemm_h<false, false><<<g, 256, SMEM_BYTES>>>(
            p_attn16, p_docT16, retrieved, nullptr, D_, D_, D_, H_, 1.0f,
            (size_t)Q_ * D_, (size_t)H_ * D_, (size_t)Q_ * H_);
    }
}

// round 10
// speedup vs baseline: 1.6553x; 1.0940x over previous
#include <cuda_runtime.h>
#include <cuda_fp16.h>
#include <math.h>
#include <stdint.h>

#define B_  8
#define Q_  512
#define D_  4096
#define H_  1024

#define STAGES  4
#define TILE    128
#define BK      32                         // k halves per stage
#define STRD_H  40                         // smem row stride in halves (bank-safe for ldmatrix)
#define A_HALVES (TILE * STRD_H)           // 5120
#define STAGE_HALVES (2 * A_HALVES)        // 10240
#define SMEM_BYTES (STAGES * STAGE_HALVES * 2)   // 81920

// ---------------- scratch (static device memory; no allocs allowed) ----------
__device__ __align__(16) __half g_q16[(size_t)B_ * Q_ * H_];     // projected queries
__device__ __align__(16) __half g_query16[(size_t)B_ * Q_ * H_]; // fp16(query)
__device__ __align__(16) __half g_WT16[(size_t)H_ * H_];         // fp16(W^T) [n][k]
__device__ __align__(16) __half g_doc16[(size_t)B_ * D_ * H_];   // fp16(doc)  [B,D,H]
__device__ __align__(16) __half g_docT16[(size_t)B_ * H_ * D_];  // fp16(doc^T)[B,H,D]
__device__ __align__(16) __half g_attn16[(size_t)B_ * Q_ * D_];  // fp16(attn) [B,Q,D]

// ---------------- helpers -----------------------------------------------------
__device__ __forceinline__ void cp_async16(uint32_t dst, const void* src) {
    asm volatile("cp.async.cg.shared.global [%0], [%1], 16;" :: "r"(dst), "l"(src));
}
#define CP_COMMIT() asm volatile("cp.async.commit_group;" ::: "memory")
#define CP_WAIT(n)  asm volatile("cp.async.wait_group %0;" :: "n"(n) : "memory")

__device__ __forceinline__ uint32_t smem_u32(const void* p) {
    uint32_t a;
    asm("{ .reg .u64 t; cvta.to.shared.u64 t, %1; cvt.u32.u64 %0, t; }" : "=r"(a) : "l"(p));
    return a;
}

__device__ __forceinline__ void ldsm_x4(uint32_t* r, uint32_t addr) {
    asm volatile("ldmatrix.sync.aligned.m8n8.x4.shared.b16 {%0,%1,%2,%3}, [%4];"
                 : "=r"(r[0]), "=r"(r[1]), "=r"(r[2]), "=r"(r[3]) : "r"(addr));
}

__device__ __forceinline__ void mma_f16(float* c, const uint32_t* a, const uint32_t* b) {
    asm volatile(
        "mma.sync.aligned.m16n8k16.row.col.f32.f16.f16.f32 "
        "{%0,%1,%2,%3}, {%4,%5,%6,%7}, {%8,%9}, {%0,%1,%2,%3};"
        : "+f"(c[0]), "+f"(c[1]), "+f"(c[2]), "+f"(c[3])
        : "r"(a[0]), "r"(a[1]), "r"(a[2]), "r"(a[3]), "r"(b[0]), "r"(b[1]));
}

// ---------------- warp-MMA FP16 GEMM (CTA 128x128, warp 32x64, ldmatrix) ------
// C[m][n] = alpha * sum_k A[m][k] * B[n][k] (+ bias[n])
// A: [M,K] K-major fp16, pitch lda. B: [N,K] K-major fp16, pitch ldb.
// grid: (N/128, M/128, batches), 256 threads, 2 CTAs/SM.
template <bool HAS_BIAS, bool OUT_HALF>
__global__ void __launch_bounds__(256, 2) wgemm_h(
    const __half* __restrict__ A, const __half* __restrict__ Bm,
    void* __restrict__ Cv, const float* __restrict__ bias,
    int K, int lda, int ldb, int ldc, float alpha,
    size_t strideA, size_t strideB, size_t strideC)
{
    extern __shared__ __half smh[];
    const uint32_t sbase = smem_u32(smh);

    const int tid  = threadIdx.x;
    const int lane = tid & 31;
    const int wid  = tid >> 5;
    const int gid  = lane >> 2;          // 0..7
    const int tig  = lane & 3;           // 0..3
    const int warp_m = (wid & 3) * 32;   // 4 warps in M
    const int warp_n = (wid >> 2) * 64;  // 2 warps in N

    const size_t batch = blockIdx.z;
    const __half* Ab = A + batch * strideA + (size_t)(blockIdx.y * TILE) * lda;
    const __half* Bb = Bm + batch * strideB + (size_t)(blockIdx.x * TILE) * ldb;

    // ldmatrix per-lane byte offsets (within a stage)
    // A x4 per mt: lanes 0-7 rows r0..7 k0, 8-15 rows 8..15 k0, 16-23 rows 0..7 k8, 24-31 rows 8..15 k8
    const uint32_t offA = ((uint32_t)(warp_m + (lane & 15)) * STRD_H + ((lane >> 4) << 3)) * 2;
    // B x4 per nt-pair p: n rows 16p + ((lane>>4)<<3) + (lane&7), k offset (lane&8)
    const uint32_t offB = ((uint32_t)(warp_n + ((lane >> 4) << 3) + (lane & 7)) * STRD_H + (lane & 8)) * 2
                          + A_HALVES * 2;

    float acc[2][8][4];
#pragma unroll
    for (int mt = 0; mt < 2; mt++)
#pragma unroll
        for (int nt = 0; nt < 8; nt++)
#pragma unroll
            for (int i = 0; i < 4; i++) acc[mt][nt][i] = 0.0f;

    const int NK = K / BK;

    auto load_stage = [&](int kb) {
        const int s = kb % STAGES;
        const uint32_t stA = sbase + s * STAGE_HALVES * 2;
        const uint32_t stB = stA + A_HALVES * 2;
        const __half* gA = Ab + kb * BK;
        const __half* gB = Bb + kb * BK;
#pragma unroll
        for (int r = 0; r < 2; r++) {
            const int c = tid + r * 256;              // 0..511 chunks
            const int rw = c >> 2, q = (c & 3) * 8;   // q in halves (16B chunks)
            cp_async16(stA + (rw * STRD_H + q) * 2, gA + (size_t)rw * lda + q);
        }
#pragma unroll
        for (int r = 0; r < 2; r++) {
            const int c = tid + r * 256;
            const int rw = c >> 2, q = (c & 3) * 8;
            cp_async16(stB + (rw * STRD_H + q) * 2, gB + (size_t)rw * ldb + q);
        }
    };

#pragma unroll
    for (int s = 0; s < STAGES - 1; s++) {
        load_stage(s);
        CP_COMMIT();
    }

    for (int kb = 0; kb < NK; kb++) {
        CP_WAIT(STAGES - 2);
        __syncthreads();

        const int kn = kb + STAGES - 1;
        if (kn < NK) load_stage(kn);
        CP_COMMIT();

        const uint32_t stOff = sbase + (kb % STAGES) * STAGE_HALVES * 2;
#pragma unroll
        for (int kk = 0; kk < BK; kk += 16) {
            uint32_t a[2][4], b[4][4];
#pragma unroll
            for (int mt = 0; mt < 2; mt++)
                ldsm_x4(a[mt], stOff + offA + (mt * 16 * STRD_H + kk) * 2);
#pragma unroll
            for (int p = 0; p < 4; p++)
                ldsm_x4(b[p], stOff + offB + (p * 16 * STRD_H + kk) * 2);
#pragma unroll
            for (int mt = 0; mt < 2; mt++)
#pragma unroll
                for (int p = 0; p < 4; p++) {
                    mma_f16(acc[mt][2 * p],     a[mt], &b[p][0]);
                    mma_f16(acc[mt][2 * p + 1], a[mt], &b[p][2]);
                }
        }
        __syncthreads();
    }

    // ---- epilogue ----
#pragma unroll
    for (int mt = 0; mt < 2; mt++) {
        const int r0 = blockIdx.y * TILE + warp_m + mt * 16 + gid;
#pragma unroll
        for (int nt = 0; nt < 8; nt++) {
            const int col = blockIdx.x * TILE + warp_n + nt * 8 + 2 * tig;
            float bx = 0.f, by = 0.f;
            if (HAS_BIAS) { bx = __ldg(bias + col); by = __ldg(bias + col + 1); }
            float2 v0, v1;
            v0.x = acc[mt][nt][0] * alpha + bx;
            v0.y = acc[mt][nt][1] * alpha + by;
            v1.x = acc[mt][nt][2] * alpha + bx;
            v1.y = acc[mt][nt][3] * alpha + by;
            if (OUT_HALF) {
                __half* Cb = (__half*)Cv + batch * strideC;
                *(__half2*)(Cb + (size_t)r0 * ldc + col) =
                    __floats2half2_rn(v0.x, v0.y);
                *(__half2*)(Cb + (size_t)(r0 + 8) * ldc + col) =
                    __floats2half2_rn(v1.x, v1.y);
            } else {
                float* Cb = (float*)Cv + batch * strideC;
                *(float2*)(Cb + (size_t)r0 * ldc + col) = v0;
                *(float2*)(Cb + (size_t)(r0 + 8) * ldc + col) = v1;
            }
        }
    }
}

// ---------------- prep: flat fp32 -> fp16 --------------------------------------
__global__ void k_cvt_h(const float* __restrict__ src, __half* __restrict__ dst) {
    size_t i = (size_t)blockIdx.x * blockDim.x + threadIdx.x;
    float4 v = ((const float4*)src)[i];
    ((__half2*)dst)[i * 2]     = __floats2half2_rn(v.x, v.y);
    ((__half2*)dst)[i * 2 + 1] = __floats2half2_rn(v.z, v.w);
}

// ---------------- prep: W [K,N] -> WT fp16 [N,K] --------------------------------
__global__ void k_prep_W(const float* __restrict__ W, __half* __restrict__ WT) {
    __shared__ __half t[32][33];
    const int bx = blockIdx.x * 32;   // n
    const int by = blockIdx.y * 32;   // k
    const int x = threadIdx.x, y = threadIdx.y;
#pragma unroll
    for (int r = 0; r < 4; r++)
        t[y + 8 * r][x] = __float2half_rn(W[(size_t)(by + y + 8 * r) * H_ + bx + x]);
    __syncthreads();
#pragma unroll
    for (int r = 0; r < 4; r++)
        WT[(size_t)(bx + y + 8 * r) * H_ + by + x] = t[x][y + 8 * r];
}

// ---------------- prep: doc -> doc16 [B,D,H] + docT16 [B,H,D] -------------------
__global__ void k_prep_doc(const float* __restrict__ doc,
                           __half* __restrict__ doc16,
                           __half* __restrict__ docT16) {
    __shared__ __half t[32][33];
    const size_t b = blockIdx.z;
    const float* Db = doc + b * (size_t)D_ * H_;
    __half* Gd = doc16 + b * (size_t)D_ * H_;
    __half* Gt = docT16 + b * (size_t)H_ * D_;
    const int bx = blockIdx.x * 32;   // h
    const int by = blockIdx.y * 32;   // d
    const int x = threadIdx.x, y = threadIdx.y;
#pragma unroll
    for (int r = 0; r < 4; r++) {
        int rw = y + 8 * r;
        __half v = __float2half_rn(Db[(size_t)(by + rw) * H_ + bx + x]);
        Gd[(size_t)(by + rw) * H_ + bx + x] = v;
        t[rw][x] = v;
    }
    __syncthreads();
#pragma unroll
    for (int r = 0; r < 4; r++)
        Gt[(size_t)(bx + y + 8 * r) * D_ + by + x] = t[x][y + 8 * r];
}

// ---------------- masked softmax over D: fp32 out (in place) + fp16 copy -------
__global__ void __launch_bounds__(256) softmax_kernel(
    float* __restrict__ attn, const int* __restrict__ mask,
    __half* __restrict__ attn16)
{
    const int row = blockIdx.x;            // b*Q_ + q
    const int b = row / Q_;
    const int4* mrow = (const int4*)(mask + (size_t)b * D_);
    float4* s4 = (float4*)(attn + (size_t)row * D_);
    __half2* h2 = (__half2*)(attn16 + (size_t)row * D_);
    const int tid = threadIdx.x;

    float v[16];
    float mx = -INFINITY;
#pragma unroll
    for (int i = 0; i < 4; i++) {
        const int c = tid + i * 256;
        int4 m = mrow[c];
        float4 x = s4[c];
        v[i * 4 + 0] = (m.x != 0) ? x.x : -INFINITY;
        v[i * 4 + 1] = (m.y != 0) ? x.y : -INFINITY;
        v[i * 4 + 2] = (m.z != 0) ? x.z : -INFINITY;
        v[i * 4 + 3] = (m.w != 0) ? x.w : -INFINITY;
        mx = fmaxf(mx, fmaxf(fmaxf(v[i * 4], v[i * 4 + 1]), fmaxf(v[i * 4 + 2], v[i * 4 + 3])));
    }

    __shared__ float red[8];
#pragma unroll
    for (int off = 16; off > 0; off >>= 1)
        mx = fmaxf(mx, __shfl_xor_sync(0xffffffffu, mx, off));
    if ((tid & 31) == 0) red[tid >> 5] = mx;
    __syncthreads();
    if (tid < 32) {
        float m2 = (tid < 8) ? red[tid] : -INFINITY;
#pragma unroll
        for (int off = 4; off > 0; off >>= 1)
            m2 = fmaxf(m2, __shfl_xor_sync(0xffffffffu, m2, off));
        if (tid == 0) red[0] = m2;
    }
    __syncthreads();
    mx = red[0];

    float sum = 0.0f;
#pragma unroll
    for (int i = 0; i < 16; i++) {
        float e = (v[i] != -INFINITY) ? expf(v[i] - mx) : 0.0f;
        v[i] = e;
        sum += e;
    }
#pragma unroll
    for (int off = 16; off > 0; off >>= 1)
        sum += __shfl_xor_sync(0xffffffffu, sum, off);
    __syncthreads();
    if ((tid & 31) == 0) red[tid >> 5] = sum;
    __syncthreads();
    if (tid < 32) {
        float s2 = (tid < 8) ? red[tid] : 0.0f;
#pragma unroll
        for (int off = 4; off > 0; off >>= 1)
            s2 += __shfl_xor_sync(0xffffffffu, s2, off);
        if (tid == 0) red[0] = s2;
    }
    __syncthreads();
    const float inv = 1.0f / red[0];

#pragma unroll
    for (int i = 0; i < 4; i++) {
        const int c = tid + i * 256;
        float4 o;
        o.x = v[i * 4 + 0] * inv;
        o.y = v[i * 4 + 1] * inv;
        o.z = v[i * 4 + 2] * inv;
        o.w = v[i * 4 + 3] * inv;
        s4[c] = o;                                   // fp32 output
        h2[c * 2]     = __floats2half2_rn(o.x, o.y); // fp16 operand for GEMM3
        h2[c * 2 + 1] = __floats2half2_rn(o.z, o.w);
    }
}

// ---------------- launch --------------------------------------------------------
extern "C" void kernel_launch(void* const* d_in, const int* in_sizes, int n_in,
                              void* d_out, int out_size)
{
    const float* query = (const float*)d_in[0];   // [B,Q,H]
    const float* doc   = (const float*)d_in[1];   // [B,D,H]
    const int*   mask  = (const int*)d_in[2];     // [B,D]
    const float* W     = (const float*)d_in[3];   // [H,H]
    const float* bias  = (const float*)d_in[4];   // [H]

    float* out = (float*)d_out;
    float* retrieved = out;                               // [B,Q,H]
    float* attn = out + (size_t)B_ * Q_ * H_;             // [B,Q,D]

    __half *p_q16, *p_query16, *p_WT16, *p_doc16, *p_docT16, *p_attn16;
    cudaGetSymbolAddress((void**)&p_q16, g_q16);
    cudaGetSymbolAddress((void**)&p_query16, g_query16);
    cudaGetSymbolAddress((void**)&p_WT16, g_WT16);
    cudaGetSymbolAddress((void**)&p_doc16, g_doc16);
    cudaGetSymbolAddress((void**)&p_docT16, g_docT16);
    cudaGetSymbolAddress((void**)&p_attn16, g_attn16);

    cudaFuncSetAttribute(wgemm_h<true, true>,
                         cudaFuncAttributeMaxDynamicSharedMemorySize, SMEM_BYTES);
    cudaFuncSetAttribute(wgemm_h<false, false>,
                         cudaFuncAttributeMaxDynamicSharedMemorySize, SMEM_BYTES);

    // prep: fp16 conversions (+ transposes)
    k_cvt_h<<<((size_t)B_ * Q_ * H_) / 4 / 256, 256>>>(query, p_query16);
    {
        dim3 g(H_ / 32, H_ / 32, 1);
        k_prep_W<<<g, dim3(32, 8)>>>(W, p_WT16);
    }
    {
        dim3 g(H_ / 32, D_ / 32, B_);
        k_prep_doc<<<g, dim3(32, 8)>>>(doc, p_doc16, p_docT16);
    }

    const float scale = 1.0f / 32.0f;   // 1/sqrt(H)

    // 1) q = query @ W + bias  (M=4096, N=1024, K=1024); B = WT16 [n][k]
    {
        dim3 g(H_ / TILE, (B_ * Q_) / TILE, 1);
        wgemm_h<true, true><<<g, 256, SMEM_BYTES>>>(
            p_query16, p_WT16, p_q16, bias, H_, H_, H_, H_, 1.0f, 0, 0, 0);
    }
    // 2) scores = q @ doc^T * scale -> attn fp32; B = doc16 [d][h]
    {
        dim3 g(D_ / TILE, Q_ / TILE, B_);
        wgemm_h<false, false><<<g, 256, SMEM_BYTES>>>(
            p_q16, p_doc16, attn, nullptr, H_, H_, H_, D_, scale,
            (size_t)Q_ * H_, (size_t)D_ * H_, (size_t)Q_ * D_);
    }
    // 3) masked softmax: fp32 weights (output) + fp16 operand copy
    softmax_kernel<<<B_ * Q_, 256>>>(attn, mask, p_attn16);
    // 4) retrieved = attn @ doc; B = docT16 [h][d], K = D
    {
        dim3 g(H_ / TILE, Q_ / TILE, B_);
        wgemm_h<false, false><<<g, 256, SMEM_BYTES>>>(
            p_attn16, p_docT16, retrieved, nullptr, D_, D_, D_, H_, 1.0f,
            (size_t)Q_ * D_, (size_t)H_ * D_, (size_t)Q_ * H_);
    }
}

// round 11
// speedup vs baseline: 1.8127x; 1.0951x over previous
#include <cuda_runtime.h>
#include <cuda_fp16.h>
#include <math.h>
#include <stdint.h>

#define B_  8
#define Q_  512
#define D_  4096
#define H_  1024

#define STAGES  3
#define TILE    128
#define BK      64                         // k halves per stage
#define STRD_H  72                         // smem row stride in halves (bank-safe for ldmatrix)
#define A_HALVES (TILE * STRD_H)           // 9216
#define STAGE_HALVES (2 * A_HALVES)        // 18432
#define SMEM_BYTES (STAGES * STAGE_HALVES * 2)   // 110592

// ---------------- scratch (static device memory; no allocs allowed) ----------
__device__ __align__(16) __half g_q16[(size_t)B_ * Q_ * H_];     // projected queries
__device__ __align__(16) __half g_query16[(size_t)B_ * Q_ * H_]; // fp16(query)
__device__ __align__(16) __half g_WT16[(size_t)H_ * H_];         // fp16(W^T) [n][k]
__device__ __align__(16) __half g_doc16[(size_t)B_ * D_ * H_];   // fp16(doc)  [B,D,H]
__device__ __align__(16) __half g_docT16[(size_t)B_ * H_ * D_];  // fp16(doc^T)[B,H,D]
__device__ __align__(16) __half g_attn16[(size_t)B_ * Q_ * D_];  // fp16(attn) [B,Q,D]

// ---------------- helpers -----------------------------------------------------
__device__ __forceinline__ void cp_async16(uint32_t dst, const void* src) {
    asm volatile("cp.async.cg.shared.global [%0], [%1], 16;" :: "r"(dst), "l"(src));
}
#define CP_COMMIT() asm volatile("cp.async.commit_group;" ::: "memory")
#define CP_WAIT(n)  asm volatile("cp.async.wait_group %0;" :: "n"(n) : "memory")

__device__ __forceinline__ uint32_t smem_u32(const void* p) {
    uint32_t a;
    asm("{ .reg .u64 t; cvta.to.shared.u64 t, %1; cvt.u32.u64 %0, t; }" : "=r"(a) : "l"(p));
    return a;
}

__device__ __forceinline__ void ldsm_x4(uint32_t* r, uint32_t addr) {
    asm volatile("ldmatrix.sync.aligned.m8n8.x4.shared.b16 {%0,%1,%2,%3}, [%4];"
                 : "=r"(r[0]), "=r"(r[1]), "=r"(r[2]), "=r"(r[3]) : "r"(addr));
}

__device__ __forceinline__ void mma_f16(float* c, const uint32_t* a, const uint32_t* b) {
    asm volatile(
        "mma.sync.aligned.m16n8k16.row.col.f32.f16.f16.f32 "
        "{%0,%1,%2,%3}, {%4,%5,%6,%7}, {%8,%9}, {%0,%1,%2,%3};"
        : "+f"(c[0]), "+f"(c[1]), "+f"(c[2]), "+f"(c[3])
        : "r"(a[0]), "r"(a[1]), "r"(a[2]), "r"(a[3]), "r"(b[0]), "r"(b[1]));
}

// ---------------- warp-MMA FP16 GEMM (CTA 128x128, warp 32x64, BK=64) ---------
// C[m][n] = alpha * sum_k A[m][k] * B[n][k] (+ bias[n])
// A: [M,K] K-major fp16, pitch lda. B: [N,K] K-major fp16, pitch ldb.
// grid: (N/128, M/128, batches), 256 threads, 2 CTAs/SM.
template <bool HAS_BIAS, bool OUT_HALF>
__global__ void __launch_bounds__(256, 2) wgemm_h(
    const __half* __restrict__ A, const __half* __restrict__ Bm,
    void* __restrict__ Cv, const float* __restrict__ bias,
    int K, int lda, int ldb, int ldc, float alpha,
    size_t strideA, size_t strideB, size_t strideC)
{
    extern __shared__ __half smh[];
    const uint32_t sbase = smem_u32(smh);

    const int tid  = threadIdx.x;
    const int lane = tid & 31;
    const int wid  = tid >> 5;
    const int gid  = lane >> 2;          // 0..7
    const int tig  = lane & 3;           // 0..3
    const int warp_m = (wid & 3) * 32;   // 4 warps in M
    const int warp_n = (wid >> 2) * 64;  // 2 warps in N

    const size_t batch = blockIdx.z;
    const __half* Ab = A + batch * strideA + (size_t)(blockIdx.y * TILE) * lda;
    const __half* Bb = Bm + batch * strideB + (size_t)(blockIdx.x * TILE) * ldb;

    // ldmatrix per-lane byte offsets (within a stage)
    const uint32_t offA = ((uint32_t)(warp_m + (lane & 15)) * STRD_H + ((lane >> 4) << 3)) * 2;
    const uint32_t offB = ((uint32_t)(warp_n + ((lane >> 4) << 3) + (lane & 7)) * STRD_H + (lane & 8)) * 2
                          + A_HALVES * 2;

    float acc[2][8][4];
#pragma unroll
    for (int mt = 0; mt < 2; mt++)
#pragma unroll
        for (int nt = 0; nt < 8; nt++)
#pragma unroll
            for (int i = 0; i < 4; i++) acc[mt][nt][i] = 0.0f;

    const int NK = K / BK;

    auto load_stage = [&](int kb) {
        const int s = kb % STAGES;
        const uint32_t stA = sbase + s * STAGE_HALVES * 2;
        const uint32_t stB = stA + A_HALVES * 2;
        const __half* gA = Ab + kb * BK;
        const __half* gB = Bb + kb * BK;
#pragma unroll
        for (int r = 0; r < 4; r++) {
            const int c = tid + r * 256;              // 0..1023 chunks
            const int rw = c >> 3, q = (c & 7) * 8;   // q in halves (16B chunks)
            cp_async16(stA + (rw * STRD_H + q) * 2, gA + (size_t)rw * lda + q);
        }
#pragma unroll
        for (int r = 0; r < 4; r++) {
            const int c = tid + r * 256;
            const int rw = c >> 3, q = (c & 7) * 8;
            cp_async16(stB + (rw * STRD_H + q) * 2, gB + (size_t)rw * ldb + q);
        }
    };

#pragma unroll
    for (int s = 0; s < STAGES - 1; s++) {
        load_stage(s);
        CP_COMMIT();
    }

    for (int kb = 0; kb < NK; kb++) {
        CP_WAIT(STAGES - 2);
        __syncthreads();

        const int kn = kb + STAGES - 1;
        if (kn < NK) load_stage(kn);
        CP_COMMIT();

        const uint32_t stOff = sbase + (kb % STAGES) * STAGE_HALVES * 2;
#pragma unroll
        for (int kk = 0; kk < BK; kk += 16) {
            uint32_t a[2][4], b[4][4];
#pragma unroll
            for (int mt = 0; mt < 2; mt++)
                ldsm_x4(a[mt], stOff + offA + (mt * 16 * STRD_H + kk) * 2);
#pragma unroll
            for (int p = 0; p < 4; p++)
                ldsm_x4(b[p], stOff + offB + (p * 16 * STRD_H + kk) * 2);
#pragma unroll
            for (int mt = 0; mt < 2; mt++)
#pragma unroll
                for (int p = 0; p < 4; p++) {
                    mma_f16(acc[mt][2 * p],     a[mt], &b[p][0]);
                    mma_f16(acc[mt][2 * p + 1], a[mt], &b[p][2]);
                }
        }
        __syncthreads();
    }

    // ---- epilogue ----
#pragma unroll
    for (int mt = 0; mt < 2; mt++) {
        const int r0 = blockIdx.y * TILE + warp_m + mt * 16 + gid;
#pragma unroll
        for (int nt = 0; nt < 8; nt++) {
            const int col = blockIdx.x * TILE + warp_n + nt * 8 + 2 * tig;
            float bx = 0.f, by = 0.f;
            if (HAS_BIAS) { bx = __ldg(bias + col); by = __ldg(bias + col + 1); }
            float2 v0, v1;
            v0.x = acc[mt][nt][0] * alpha + bx;
            v0.y = acc[mt][nt][1] * alpha + by;
            v1.x = acc[mt][nt][2] * alpha + bx;
            v1.y = acc[mt][nt][3] * alpha + by;
            if (OUT_HALF) {
                __half* Cb = (__half*)Cv + batch * strideC;
                *(__half2*)(Cb + (size_t)r0 * ldc + col) =
                    __floats2half2_rn(v0.x, v0.y);
                *(__half2*)(Cb + (size_t)(r0 + 8) * ldc + col) =
                    __floats2half2_rn(v1.x, v1.y);
            } else {
                float* Cb = (float*)Cv + batch * strideC;
                *(float2*)(Cb + (size_t)r0 * ldc + col) = v0;
                *(float2*)(Cb + (size_t)(r0 + 8) * ldc + col) = v1;
            }
        }
    }
}

// ---------------- prep: flat fp32 -> fp16 --------------------------------------
__global__ void k_cvt_h(const float* __restrict__ src, __half* __restrict__ dst) {
    size_t i = (size_t)blockIdx.x * blockDim.x + threadIdx.x;
    float4 v = ((const float4*)src)[i];
    ((__half2*)dst)[i * 2]     = __floats2half2_rn(v.x, v.y);
    ((__half2*)dst)[i * 2 + 1] = __floats2half2_rn(v.z, v.w);
}

// ---------------- prep: W [K,N] -> WT fp16 [N,K] --------------------------------
__global__ void k_prep_W(const float* __restrict__ W, __half* __restrict__ WT) {
    __shared__ __half t[32][33];
    const int bx = blockIdx.x * 32;   // n
    const int by = blockIdx.y * 32;   // k
    const int x = threadIdx.x, y = threadIdx.y;
#pragma unroll
    for (int r = 0; r < 4; r++)
        t[y + 8 * r][x] = __float2half_rn(W[(size_t)(by + y + 8 * r) * H_ + bx + x]);
    __syncthreads();
#pragma unroll
    for (int r = 0; r < 4; r++)
        WT[(size_t)(bx + y + 8 * r) * H_ + by + x] = t[x][y + 8 * r];
}

// ---------------- prep: doc -> doc16 [B,D,H] + docT16 [B,H,D] -------------------
__global__ void k_prep_doc(const float* __restrict__ doc,
                           __half* __restrict__ doc16,
                           __half* __restrict__ docT16) {
    __shared__ __half t[32][33];
    const size_t b = blockIdx.z;
    const float* Db = doc + b * (size_t)D_ * H_;
    __half* Gd = doc16 + b * (size_t)D_ * H_;
    __half* Gt = docT16 + b * (size_t)H_ * D_;
    const int bx = blockIdx.x * 32;   // h
    const int by = blockIdx.y * 32;   // d
    const int x = threadIdx.x, y = threadIdx.y;
#pragma unroll
    for (int r = 0; r < 4; r++) {
        int rw = y + 8 * r;
        __half v = __float2half_rn(Db[(size_t)(by + rw) * H_ + bx + x]);
        Gd[(size_t)(by + rw) * H_ + bx + x] = v;
        t[rw][x] = v;
    }
    __syncthreads();
#pragma unroll
    for (int r = 0; r < 4; r++)
        Gt[(size_t)(bx + y + 8 * r) * D_ + by + x] = t[x][y + 8 * r];
}

// ---------------- masked softmax over D: fp32 out (in place) + fp16 copy -------
__global__ void __launch_bounds__(256) softmax_kernel(
    float* __restrict__ attn, const int* __restrict__ mask,
    __half* __restrict__ attn16)
{
    const int row = blockIdx.x;            // b*Q_ + q
    const int b = row / Q_;
    const int4* mrow = (const int4*)(mask + (size_t)b * D_);
    float4* s4 = (float4*)(attn + (size_t)row * D_);
    __half2* h2 = (__half2*)(attn16 + (size_t)row * D_);
    const int tid = threadIdx.x;

    float v[16];
    float mx = -INFINITY;
#pragma unroll
    for (int i = 0; i < 4; i++) {
        const int c = tid + i * 256;
        int4 m = mrow[c];
        float4 x = s4[c];
        v[i * 4 + 0] = (m.x != 0) ? x.x : -INFINITY;
        v[i * 4 + 1] = (m.y != 0) ? x.y : -INFINITY;
        v[i * 4 + 2] = (m.z != 0) ? x.z : -INFINITY;
        v[i * 4 + 3] = (m.w != 0) ? x.w : -INFINITY;
        mx = fmaxf(mx, fmaxf(fmaxf(v[i * 4], v[i * 4 + 1]), fmaxf(v[i * 4 + 2], v[i * 4 + 3])));
    }

    __shared__ float red[8];
#pragma unroll
    for (int off = 16; off > 0; off >>= 1)
        mx = fmaxf(mx, __shfl_xor_sync(0xffffffffu, mx, off));
    if ((tid & 31) == 0) red[tid >> 5] = mx;
    __syncthreads();
    if (tid < 32) {
        float m2 = (tid < 8) ? red[tid] : -INFINITY;
#pragma unroll
        for (int off = 4; off > 0; off >>= 1)
            m2 = fmaxf(m2, __shfl_xor_sync(0xffffffffu, m2, off));
        if (tid == 0) red[0] = m2;
    }
    __syncthreads();
    mx = red[0];

    float sum = 0.0f;
#pragma unroll
    for (int i = 0; i < 16; i++) {
        float e = (v[i] != -INFINITY) ? expf(v[i] - mx) : 0.0f;
        v[i] = e;
        sum += e;
    }
#pragma unroll
    for (int off = 16; off > 0; off >>= 1)
        sum += __shfl_xor_sync(0xffffffffu, sum, off);
    __syncthreads();
    if ((tid & 31) == 0) red[tid >> 5] = sum;
    __syncthreads();
    if (tid < 32) {
        float s2 = (tid < 8) ? red[tid] : 0.0f;
#pragma unroll
        for (int off = 4; off > 0; off >>= 1)
            s2 += __shfl_xor_sync(0xffffffffu, s2, off);
        if (tid == 0) red[0] = s2;
    }
    __syncthreads();
    const float inv = 1.0f / red[0];

#pragma unroll
    for (int i = 0; i < 4; i++) {
        const int c = tid + i * 256;
        float4 o;
        o.x = v[i * 4 + 0] * inv;
        o.y = v[i * 4 + 1] * inv;
        o.z = v[i * 4 + 2] * inv;
        o.w = v[i * 4 + 3] * inv;
        s4[c] = o;                                   // fp32 output
        h2[c * 2]     = __floats2half2_rn(o.x, o.y); // fp16 operand for GEMM3
        h2[c * 2 + 1] = __floats2half2_rn(o.z, o.w);
    }
}

// ---------------- launch --------------------------------------------------------
extern "C" void kernel_launch(void* const* d_in, const int* in_sizes, int n_in,
                              void* d_out, int out_size)
{
    const float* query = (const float*)d_in[0];   // [B,Q,H]
    const float* doc   = (const float*)d_in[1];   // [B,D,H]
    const int*   mask  = (const int*)d_in[2];     // [B,D]
    const float* W     = (const float*)d_in[3];   // [H,H]
    const float* bias  = (const float*)d_in[4];   // [H]

    float* out = (float*)d_out;
    float* retrieved = out;                               // [B,Q,H]
    float* attn = out + (size_t)B_ * Q_ * H_;             // [B,Q,D]

    __half *p_q16, *p_query16, *p_WT16, *p_doc16, *p_docT16, *p_attn16;
    cudaGetSymbolAddress((void**)&p_q16, g_q16);
    cudaGetSymbolAddress((void**)&p_query16, g_query16);
    cudaGetSymbolAddress((void**)&p_WT16, g_WT16);
    cudaGetSymbolAddress((void**)&p_doc16, g_doc16);
    cudaGetSymbolAddress((void**)&p_docT16, g_docT16);
    cudaGetSymbolAddress((void**)&p_attn16, g_attn16);

    cudaFuncSetAttribute(wgemm_h<true, true>,
                         cudaFuncAttributeMaxDynamicSharedMemorySize, SMEM_BYTES);
    cudaFuncSetAttribute(wgemm_h<false, false>,
                         cudaFuncAttributeMaxDynamicSharedMemorySize, SMEM_BYTES);

    // prep: fp16 conversions (+ transposes)
    k_cvt_h<<<((size_t)B_ * Q_ * H_) / 4 / 256, 256>>>(query, p_query16);
    {
        dim3 g(H_ / 32, H_ / 32, 1);
        k_prep_W<<<g, dim3(32, 8)>>>(W, p_WT16);
    }
    {
        dim3 g(H_ / 32, D_ / 32, B_);
        k_prep_doc<<<g, dim3(32, 8)>>>(doc, p_doc16, p_docT16);
    }

    const float scale = 1.0f / 32.0f;   // 1/sqrt(H)

    // 1) q = query @ W + bias  (M=4096, N=1024, K=1024); B = WT16 [n][k]
    {
        dim3 g(H_ / TILE, (B_ * Q_) / TILE, 1);
        wgemm_h<true, true><<<g, 256, SMEM_BYTES>>>(
            p_query16, p_WT16, p_q16, bias, H_, H_, H_, H_, 1.0f, 0, 0, 0);
    }
    // 2) scores = q @ doc^T * scale -> attn fp32; B = doc16 [d][h]
    {
        dim3 g(D_ / TILE, Q_ / TILE, B_);
        wgemm_h<false, false><<<g, 256, SMEM_BYTES>>>(
            p_q16, p_doc16, attn, nullptr, H_, H_, H_, D_, scale,
            (size_t)Q_ * H_, (size_t)D_ * H_, (size_t)Q_ * D_);
    }
    // 3) masked softmax: fp32 weights (output) + fp16 operand copy
    softmax_kernel<<<B_ * Q_, 256>>>(attn, mask, p_attn16);
    // 4) retrieved = attn @ doc; B = docT16 [h][d], K = D
    {
        dim3 g(H_ / TILE, Q_ / TILE, B_);
        wgemm_h<false, false><<<g, 256, SMEM_BYTES>>>(
            p_attn16, p_docT16, retrieved, nullptr, D_, D_, D_, H_, 1.0f,
            (size_t)Q_ * D_, (size_t)H_ * D_, (size_t)Q_ * H_);
    }
}

// round 12
// speedup vs baseline: 1.8743x; 1.0340x over previous
#include <cuda_runtime.h>
#include <cuda_fp16.h>
#include <math.h>
#include <stdint.h>

#define B_  8
#define Q_  512
#define D_  4096
#define H_  1024

#define STAGES  3
#define TILE    128
#define BK      64                         // k halves per stage
#define STRD_H  72                         // K-major smem row stride (halves)
#define STRD_BN 136                        // trans-B smem row stride (halves)
#define A_HALVES (TILE * STRD_H)           // 9216
#define B_REGION 9216                      // >= max(128*72, 64*136=8704)
#define STAGE_HALVES (A_HALVES + B_REGION) // 18432
#define SMEM_BYTES (STAGES * STAGE_HALVES * 2)   // 110592

// ---------------- scratch (static device memory; no allocs allowed) ----------
__device__ __align__(16) __half g_q16[(size_t)B_ * Q_ * H_];     // projected queries
__device__ __align__(16) __half g_query16[(size_t)B_ * Q_ * H_]; // fp16(query)
__device__ __align__(16) __half g_W16[(size_t)H_ * H_];          // fp16(W) [k][n]
__device__ __align__(16) __half g_doc16[(size_t)B_ * D_ * H_];   // fp16(doc) [B,D,H]
__device__ __align__(16) __half g_attn16[(size_t)B_ * Q_ * D_];  // fp16(attn) [B,Q,D]

// ---------------- helpers -----------------------------------------------------
__device__ __forceinline__ void cp_async16(uint32_t dst, const void* src) {
    asm volatile("cp.async.cg.shared.global [%0], [%1], 16;" :: "r"(dst), "l"(src));
}
#define CP_COMMIT() asm volatile("cp.async.commit_group;" ::: "memory")
#define CP_WAIT(n)  asm volatile("cp.async.wait_group %0;" :: "n"(n) : "memory")

__device__ __forceinline__ uint32_t smem_u32(const void* p) {
    uint32_t a;
    asm("{ .reg .u64 t; cvta.to.shared.u64 t, %1; cvt.u32.u64 %0, t; }" : "=r"(a) : "l"(p));
    return a;
}

__device__ __forceinline__ void ldsm_x4(uint32_t* r, uint32_t addr) {
    asm volatile("ldmatrix.sync.aligned.m8n8.x4.shared.b16 {%0,%1,%2,%3}, [%4];"
                 : "=r"(r[0]), "=r"(r[1]), "=r"(r[2]), "=r"(r[3]) : "r"(addr));
}
__device__ __forceinline__ void ldsm_x4_t(uint32_t* r, uint32_t addr) {
    asm volatile("ldmatrix.sync.aligned.m8n8.x4.trans.shared.b16 {%0,%1,%2,%3}, [%4];"
                 : "=r"(r[0]), "=r"(r[1]), "=r"(r[2]), "=r"(r[3]) : "r"(addr));
}

__device__ __forceinline__ void mma_f16(float* c, const uint32_t* a, const uint32_t* b) {
    asm volatile(
        "mma.sync.aligned.m16n8k16.row.col.f32.f16.f16.f32 "
        "{%0,%1,%2,%3}, {%4,%5,%6,%7}, {%8,%9}, {%0,%1,%2,%3};"
        : "+f"(c[0]), "+f"(c[1]), "+f"(c[2]), "+f"(c[3])
        : "r"(a[0]), "r"(a[1]), "r"(a[2]), "r"(a[3]), "r"(b[0]), "r"(b[1]));
}

// ---------------- warp-MMA FP16 GEMM (CTA 128x128, warp 32x64, BK=64) ---------
// C[m][n] = alpha * sum_k A[m][k] * op(B) (+ bias[n])
//   A: [M,K] K-major fp16, pitch lda.
//   B_TRANS=0: B is [N,K] K-major fp16, pitch ldb. (non-trans ldmatrix)
//   B_TRANS=1: B is [K,N] row-major fp16, pitch ldb. (trans ldmatrix)
// grid: (N/128, M/128, batches), 256 threads, 2 CTAs/SM.
template <bool B_TRANS, bool HAS_BIAS, bool OUT_HALF>
__global__ void __launch_bounds__(256, 2) wgemm_h(
    const __half* __restrict__ A, const __half* __restrict__ Bm,
    void* __restrict__ Cv, const float* __restrict__ bias,
    int K, int lda, int ldb, int ldc, float alpha,
    size_t strideA, size_t strideB, size_t strideC)
{
    extern __shared__ __half smh[];
    const uint32_t sbase = smem_u32(smh);

    const int tid  = threadIdx.x;
    const int lane = tid & 31;
    const int wid  = tid >> 5;
    const int gid  = lane >> 2;          // 0..7
    const int tig  = lane & 3;           // 0..3
    const int warp_m = (wid & 3) * 32;   // 4 warps in M
    const int warp_n = (wid >> 2) * 64;  // 2 warps in N

    const size_t batch = blockIdx.z;
    const __half* Ab = A + batch * strideA + (size_t)(blockIdx.y * TILE) * lda;
    const __half* Bb;
    if (B_TRANS)
        Bb = Bm + batch * strideB + blockIdx.x * TILE;               // [K,N] cols
    else
        Bb = Bm + batch * strideB + (size_t)(blockIdx.x * TILE) * ldb; // [N,K] rows

    // ldmatrix per-lane static byte offsets (within a stage)
    const uint32_t offA = ((uint32_t)(warp_m + (lane & 15)) * STRD_H + ((lane >> 4) << 3)) * 2;
    // non-trans B (K-major rows)
    const uint32_t offB = ((uint32_t)(warp_n + ((lane >> 4) << 3) + (lane & 7)) * STRD_H + (lane & 8)) * 2
                          + A_HALVES * 2;
    // trans B ([K,N] rows): bit3 of lane -> k-group (+8 rows), bit4 -> n-group (+8 cols)
    const uint32_t offBT = ((uint32_t)((lane & 7) + ((lane >> 3) & 1) * 8) * STRD_BN
                            + warp_n + ((lane >> 4) << 3)) * 2
                          + A_HALVES * 2;

    float acc[2][8][4];
#pragma unroll
    for (int mt = 0; mt < 2; mt++)
#pragma unroll
        for (int nt = 0; nt < 8; nt++)
#pragma unroll
            for (int i = 0; i < 4; i++) acc[mt][nt][i] = 0.0f;

    const int NK = K / BK;

    auto load_stage = [&](int kb) {
        const int s = kb % STAGES;
        const uint32_t stA = sbase + s * STAGE_HALVES * 2;
        const uint32_t stB = stA + A_HALVES * 2;
        const __half* gA = Ab + kb * BK;
#pragma unroll
        for (int r = 0; r < 4; r++) {
            const int c = tid + r * 256;              // 0..1023 chunks
            const int rw = c >> 3, q = (c & 7) * 8;   // 128 rows x 8 chunks
            cp_async16(stA + (rw * STRD_H + q) * 2, gA + (size_t)rw * lda + q);
        }
        if (B_TRANS) {
            const __half* gB = Bb + (size_t)(kb * BK) * ldb;
#pragma unroll
            for (int r = 0; r < 4; r++) {
                const int c = tid + r * 256;              // 0..1023
                const int rw = c >> 4, q = (c & 15) * 8;  // 64 rows x 16 chunks
                cp_async16(stB + (rw * STRD_BN + q) * 2, gB + (size_t)rw * ldb + q);
            }
        } else {
            const __half* gB = Bb + kb * BK;
#pragma unroll
            for (int r = 0; r < 4; r++) {
                const int c = tid + r * 256;
                const int rw = c >> 3, q = (c & 7) * 8;
                cp_async16(stB + (rw * STRD_H + q) * 2, gB + (size_t)rw * ldb + q);
            }
        }
    };

#pragma unroll
    for (int s = 0; s < STAGES - 1; s++) {
        load_stage(s);
        CP_COMMIT();
    }

    for (int kb = 0; kb < NK; kb++) {
        CP_WAIT(STAGES - 2);
        __syncthreads();

        const int kn = kb + STAGES - 1;
        if (kn < NK) load_stage(kn);
        CP_COMMIT();

        const uint32_t stOff = sbase + (kb % STAGES) * STAGE_HALVES * 2;
#pragma unroll
        for (int kk = 0; kk < BK; kk += 16) {
            uint32_t a[2][4], b[4][4];
#pragma unroll
            for (int mt = 0; mt < 2; mt++)
                ldsm_x4(a[mt], stOff + offA + (mt * 16 * STRD_H + kk) * 2);
#pragma unroll
            for (int p = 0; p < 4; p++) {
                if (B_TRANS)
                    ldsm_x4_t(b[p], stOff + offBT + (kk * STRD_BN + p * 16) * 2);
                else
                    ldsm_x4(b[p], stOff + offB + (p * 16 * STRD_H + kk) * 2);
            }
#pragma unroll
            for (int mt = 0; mt < 2; mt++)
#pragma unroll
                for (int p = 0; p < 4; p++) {
                    mma_f16(acc[mt][2 * p],     a[mt], &b[p][0]);
                    mma_f16(acc[mt][2 * p + 1], a[mt], &b[p][2]);
                }
        }
        __syncthreads();
    }

    // ---- epilogue ----
#pragma unroll
    for (int mt = 0; mt < 2; mt++) {
        const int r0 = blockIdx.y * TILE + warp_m + mt * 16 + gid;
#pragma unroll
        for (int nt = 0; nt < 8; nt++) {
            const int col = blockIdx.x * TILE + warp_n + nt * 8 + 2 * tig;
            float bx = 0.f, by = 0.f;
            if (HAS_BIAS) { bx = __ldg(bias + col); by = __ldg(bias + col + 1); }
            float2 v0, v1;
            v0.x = acc[mt][nt][0] * alpha + bx;
            v0.y = acc[mt][nt][1] * alpha + by;
            v1.x = acc[mt][nt][2] * alpha + bx;
            v1.y = acc[mt][nt][3] * alpha + by;
            if (OUT_HALF) {
                __half* Cb = (__half*)Cv + batch * strideC;
                *(__half2*)(Cb + (size_t)r0 * ldc + col) =
                    __floats2half2_rn(v0.x, v0.y);
                *(__half2*)(Cb + (size_t)(r0 + 8) * ldc + col) =
                    __floats2half2_rn(v1.x, v1.y);
            } else {
                float* Cb = (float*)Cv + batch * strideC;
                *(float2*)(Cb + (size_t)r0 * ldc + col) = v0;
                *(float2*)(Cb + (size_t)(r0 + 8) * ldc + col) = v1;
            }
        }
    }
}

// ---------------- prep: flat fp32 -> fp16 --------------------------------------
__global__ void k_cvt_h(const float* __restrict__ src, __half* __restrict__ dst) {
    size_t i = (size_t)blockIdx.x * blockDim.x + threadIdx.x;
    float4 v = ((const float4*)src)[i];
    ((__half2*)dst)[i * 2]     = __floats2half2_rn(v.x, v.y);
    ((__half2*)dst)[i * 2 + 1] = __floats2half2_rn(v.z, v.w);
}

// ---------------- masked softmax over D: fp32 out (in place) + fp16 copy -------
__global__ void __launch_bounds__(256) softmax_kernel(
    float* __restrict__ attn, const int* __restrict__ mask,
    __half* __restrict__ attn16)
{
    const int row = blockIdx.x;            // b*Q_ + q
    const int b = row / Q_;
    const int4* mrow = (const int4*)(mask + (size_t)b * D_);
    float4* s4 = (float4*)(attn + (size_t)row * D_);
    __half2* h2 = (__half2*)(attn16 + (size_t)row * D_);
    const int tid = threadIdx.x;

    float v[16];
    float mx = -INFINITY;
#pragma unroll
    for (int i = 0; i < 4; i++) {
        const int c = tid + i * 256;
        int4 m = mrow[c];
        float4 x = s4[c];
        v[i * 4 + 0] = (m.x != 0) ? x.x : -INFINITY;
        v[i * 4 + 1] = (m.y != 0) ? x.y : -INFINITY;
        v[i * 4 + 2] = (m.z != 0) ? x.z : -INFINITY;
        v[i * 4 + 3] = (m.w != 0) ? x.w : -INFINITY;
        mx = fmaxf(mx, fmaxf(fmaxf(v[i * 4], v[i * 4 + 1]), fmaxf(v[i * 4 + 2], v[i * 4 + 3])));
    }

    __shared__ float red[8];
#pragma unroll
    for (int off = 16; off > 0; off >>= 1)
        mx = fmaxf(mx, __shfl_xor_sync(0xffffffffu, mx, off));
    if ((tid & 31) == 0) red[tid >> 5] = mx;
    __syncthreads();
    if (tid < 32) {
        float m2 = (tid < 8) ? red[tid] : -INFINITY;
#pragma unroll
        for (int off = 4; off > 0; off >>= 1)
            m2 = fmaxf(m2, __shfl_xor_sync(0xffffffffu, m2, off));
        if (tid == 0) red[0] = m2;
    }
    __syncthreads();
    mx = red[0];

    float sum = 0.0f;
#pragma unroll
    for (int i = 0; i < 16; i++) {
        float e = (v[i] != -INFINITY) ? expf(v[i] - mx) : 0.0f;
        v[i] = e;
        sum += e;
    }
#pragma unroll
    for (int off = 16; off > 0; off >>= 1)
        sum += __shfl_xor_sync(0xffffffffu, sum, off);
    __syncthreads();
    if ((tid & 31) == 0) red[tid >> 5] = sum;
    __syncthreads();
    if (tid < 32) {
        float s2 = (tid < 8) ? red[tid] : 0.0f;
#pragma unroll
        for (int off = 4; off > 0; off >>= 1)
            s2 += __shfl_xor_sync(0xffffffffu, s2, off);
        if (tid == 0) red[0] = s2;
    }
    __syncthreads();
    const float inv = 1.0f / red[0];

#pragma unroll
    for (int i = 0; i < 4; i++) {
        const int c = tid + i * 256;
        float4 o;
        o.x = v[i * 4 + 0] * inv;
        o.y = v[i * 4 + 1] * inv;
        o.z = v[i * 4 + 2] * inv;
        o.w = v[i * 4 + 3] * inv;
        s4[c] = o;                                   // fp32 output
        h2[c * 2]     = __floats2half2_rn(o.x, o.y); // fp16 operand for GEMM3
        h2[c * 2 + 1] = __floats2half2_rn(o.z, o.w);
    }
}

// ---------------- launch --------------------------------------------------------
extern "C" void kernel_launch(void* const* d_in, const int* in_sizes, int n_in,
                              void* d_out, int out_size)
{
    const float* query = (const float*)d_in[0];   // [B,Q,H]
    const float* doc   = (const float*)d_in[1];   // [B,D,H]
    const int*   mask  = (const int*)d_in[2];     // [B,D]
    const float* W     = (const float*)d_in[3];   // [H,H]
    const float* bias  = (const float*)d_in[4];   // [H]

    float* out = (float*)d_out;
    float* retrieved = out;                               // [B,Q,H]
    float* attn = out + (size_t)B_ * Q_ * H_;             // [B,Q,D]

    __half *p_q16, *p_query16, *p_W16, *p_doc16, *p_attn16;
    cudaGetSymbolAddress((void**)&p_q16, g_q16);
    cudaGetSymbolAddress((void**)&p_query16, g_query16);
    cudaGetSymbolAddress((void**)&p_W16, g_W16);
    cudaGetSymbolAddress((void**)&p_doc16, g_doc16);
    cudaGetSymbolAddress((void**)&p_attn16, g_attn16);

    cudaFuncSetAttribute(wgemm_h<true, true, true>,
                         cudaFuncAttributeMaxDynamicSharedMemorySize, SMEM_BYTES);
    cudaFuncSetAttribute(wgemm_h<false, false, false>,
                         cudaFuncAttributeMaxDynamicSharedMemorySize, SMEM_BYTES);
    cudaFuncSetAttribute(wgemm_h<true, false, false>,
                         cudaFuncAttributeMaxDynamicSharedMemorySize, SMEM_BYTES);

    // prep: flat fp16 conversions (no transposes anywhere)
    k_cvt_h<<<((size_t)B_ * Q_ * H_) / 4 / 256, 256>>>(query, p_query16);
    k_cvt_h<<<((size_t)H_ * H_) / 4 / 256, 256>>>(W, p_W16);
    k_cvt_h<<<((size_t)B_ * D_ * H_) / 4 / 256, 256>>>(doc, p_doc16);

    const float scale = 1.0f / 32.0f;   // 1/sqrt(H)

    // 1) q = query @ W + bias; B = W16 [k][n] (trans path)
    {
        dim3 g(H_ / TILE, (B_ * Q_) / TILE, 1);
        wgemm_h<true, true, true><<<g, 256, SMEM_BYTES>>>(
            p_query16, p_W16, p_q16, bias, H_, H_, H_, H_, 1.0f, 0, 0, 0);
    }
    // 2) scores = q @ doc^T * scale -> attn fp32; B = doc16 [d][h] = [N,K] (non-trans)
    {
        dim3 g(D_ / TILE, Q_ / TILE, B_);
        wgemm_h<false, false, false><<<g, 256, SMEM_BYTES>>>(
            p_q16, p_doc16, attn, nullptr, H_, H_, H_, D_, scale,
            (size_t)Q_ * H_, (size_t)D_ * H_, (size_t)Q_ * D_);
    }
    // 3) masked softmax: fp32 weights (output) + fp16 operand copy
    softmax_kernel<<<B_ * Q_, 256>>>(attn, mask, p_attn16);
    // 4) retrieved = attn @ doc; B = doc16 [d][h] = [K,N] (trans path), K = D
    {
        dim3 g(H_ / TILE, Q_ / TILE, B_);
        wgemm_h<true, false, false><<<g, 256, SMEM_BYTES>>>(
            p_attn16, p_doc16, retrieved, nullptr, D_, D_, H_, H_, 1.0f,
            (size_t)Q_ * D_, (size_t)D_ * H_, (size_t)Q_ * H_);
    }
}

// round 13
// speedup vs baseline: 1.8745x; 1.0001x over previous
#include <cuda_runtime.h>
#include <cuda_fp16.h>
#include <math.h>
#include <stdint.h>

#define B_  8
#define Q_  512
#define D_  4096
#define H_  1024

#define STAGES  3
#define TILE    128
#define BK      64                         // k halves per stage
#define STRD_H  72                         // K-major smem row stride (halves)
#define STRD_BN 136                        // trans-B smem row stride (halves)
#define A_HALVES (TILE * STRD_H)           // 9216
#define B_REGION 9216                      // >= max(128*72, 64*136=8704)
#define STAGE_HALVES (A_HALVES + B_REGION) // 18432
#define SMEM_BYTES (STAGES * STAGE_HALVES * 2)   // 110592

// ---------------- scratch (static device memory; no allocs allowed) ----------
__device__ __align__(16) __half g_q16[(size_t)B_ * Q_ * H_];     // projected queries
__device__ __align__(16) __half g_query16[(size_t)B_ * Q_ * H_]; // fp16(query)
__device__ __align__(16) __half g_W16[(size_t)H_ * H_];          // fp16(W) [k][n]
__device__ __align__(16) __half g_doc16[(size_t)B_ * D_ * H_];   // fp16(doc) [B,D,H]
__device__ __align__(16) __half g_attn16[(size_t)B_ * Q_ * D_];  // fp16(attn) [B,Q,D]
__device__ float g_mx[B_ * Q_];                                   // softmax row max
__device__ float g_inv[B_ * Q_];                                  // softmax row 1/sum

// ---------------- helpers -----------------------------------------------------
__device__ __forceinline__ void cp_async16(uint32_t dst, const void* src) {
    asm volatile("cp.async.cg.shared.global [%0], [%1], 16;" :: "r"(dst), "l"(src));
}
#define CP_COMMIT() asm volatile("cp.async.commit_group;" ::: "memory")
#define CP_WAIT(n)  asm volatile("cp.async.wait_group %0;" :: "n"(n) : "memory")

__device__ __forceinline__ uint32_t smem_u32(const void* p) {
    uint32_t a;
    asm("{ .reg .u64 t; cvta.to.shared.u64 t, %1; cvt.u32.u64 %0, t; }" : "=r"(a) : "l"(p));
    return a;
}

__device__ __forceinline__ void ldsm_x4(uint32_t* r, uint32_t addr) {
    asm volatile("ldmatrix.sync.aligned.m8n8.x4.shared.b16 {%0,%1,%2,%3}, [%4];"
                 : "=r"(r[0]), "=r"(r[1]), "=r"(r[2]), "=r"(r[3]) : "r"(addr));
}
__device__ __forceinline__ void ldsm_x4_t(uint32_t* r, uint32_t addr) {
    asm volatile("ldmatrix.sync.aligned.m8n8.x4.trans.shared.b16 {%0,%1,%2,%3}, [%4];"
                 : "=r"(r[0]), "=r"(r[1]), "=r"(r[2]), "=r"(r[3]) : "r"(addr));
}

__device__ __forceinline__ void mma_f16(float* c, const uint32_t* a, const uint32_t* b) {
    asm volatile(
        "mma.sync.aligned.m16n8k16.row.col.f32.f16.f16.f32 "
        "{%0,%1,%2,%3}, {%4,%5,%6,%7}, {%8,%9}, {%0,%1,%2,%3};"
        : "+f"(c[0]), "+f"(c[1]), "+f"(c[2]), "+f"(c[3])
        : "r"(a[0]), "r"(a[1]), "r"(a[2]), "r"(a[3]), "r"(b[0]), "r"(b[1]));
}

// ---------------- warp-MMA FP16 GEMM (CTA 128x128, warp 32x64, BK=64) ---------
template <bool B_TRANS, bool HAS_BIAS, bool OUT_HALF>
__global__ void __launch_bounds__(256, 2) wgemm_h(
    const __half* __restrict__ A, const __half* __restrict__ Bm,
    void* __restrict__ Cv, const float* __restrict__ bias,
    int K, int lda, int ldb, int ldc, float alpha,
    size_t strideA, size_t strideB, size_t strideC)
{
    extern __shared__ __half smh[];
    const uint32_t sbase = smem_u32(smh);

    const int tid  = threadIdx.x;
    const int lane = tid & 31;
    const int wid  = tid >> 5;
    const int gid  = lane >> 2;
    const int tig  = lane & 3;
    const int warp_m = (wid & 3) * 32;
    const int warp_n = (wid >> 2) * 64;

    const size_t batch = blockIdx.z;
    const __half* Ab = A + batch * strideA + (size_t)(blockIdx.y * TILE) * lda;
    const __half* Bb;
    if (B_TRANS)
        Bb = Bm + batch * strideB + blockIdx.x * TILE;
    else
        Bb = Bm + batch * strideB + (size_t)(blockIdx.x * TILE) * ldb;

    const uint32_t offA = ((uint32_t)(warp_m + (lane & 15)) * STRD_H + ((lane >> 4) << 3)) * 2;
    const uint32_t offB = ((uint32_t)(warp_n + ((lane >> 4) << 3) + (lane & 7)) * STRD_H + (lane & 8)) * 2
                          + A_HALVES * 2;
    const uint32_t offBT = ((uint32_t)((lane & 7) + ((lane >> 3) & 1) * 8) * STRD_BN
                            + warp_n + ((lane >> 4) << 3)) * 2
                          + A_HALVES * 2;

    float acc[2][8][4];
#pragma unroll
    for (int mt = 0; mt < 2; mt++)
#pragma unroll
        for (int nt = 0; nt < 8; nt++)
#pragma unroll
            for (int i = 0; i < 4; i++) acc[mt][nt][i] = 0.0f;

    const int NK = K / BK;

    auto load_stage = [&](int kb) {
        const int s = kb % STAGES;
        const uint32_t stA = sbase + s * STAGE_HALVES * 2;
        const uint32_t stB = stA + A_HALVES * 2;
        const __half* gA = Ab + kb * BK;
#pragma unroll
        for (int r = 0; r < 4; r++) {
            const int c = tid + r * 256;
            const int rw = c >> 3, q = (c & 7) * 8;
            cp_async16(stA + (rw * STRD_H + q) * 2, gA + (size_t)rw * lda + q);
        }
        if (B_TRANS) {
            const __half* gB = Bb + (size_t)(kb * BK) * ldb;
#pragma unroll
            for (int r = 0; r < 4; r++) {
                const int c = tid + r * 256;
                const int rw = c >> 4, q = (c & 15) * 8;
                cp_async16(stB + (rw * STRD_BN + q) * 2, gB + (size_t)rw * ldb + q);
            }
        } else {
            const __half* gB = Bb + kb * BK;
#pragma unroll
            for (int r = 0; r < 4; r++) {
                const int c = tid + r * 256;
                const int rw = c >> 3, q = (c & 7) * 8;
                cp_async16(stB + (rw * STRD_H + q) * 2, gB + (size_t)rw * ldb + q);
            }
        }
    };

#pragma unroll
    for (int s = 0; s < STAGES - 1; s++) {
        load_stage(s);
        CP_COMMIT();
    }

    for (int kb = 0; kb < NK; kb++) {
        CP_WAIT(STAGES - 2);
        __syncthreads();

        const int kn = kb + STAGES - 1;
        if (kn < NK) load_stage(kn);
        CP_COMMIT();

        const uint32_t stOff = sbase + (kb % STAGES) * STAGE_HALVES * 2;
#pragma unroll
        for (int kk = 0; kk < BK; kk += 16) {
            uint32_t a[2][4], b[4][4];
#pragma unroll
            for (int mt = 0; mt < 2; mt++)
                ldsm_x4(a[mt], stOff + offA + (mt * 16 * STRD_H + kk) * 2);
#pragma unroll
            for (int p = 0; p < 4; p++) {
                if (B_TRANS)
                    ldsm_x4_t(b[p], stOff + offBT + (kk * STRD_BN + p * 16) * 2);
                else
                    ldsm_x4(b[p], stOff + offB + (p * 16 * STRD_H + kk) * 2);
            }
#pragma unroll
            for (int mt = 0; mt < 2; mt++)
#pragma unroll
                for (int p = 0; p < 4; p++) {
                    mma_f16(acc[mt][2 * p],     a[mt], &b[p][0]);
                    mma_f16(acc[mt][2 * p + 1], a[mt], &b[p][2]);
                }
        }
        __syncthreads();
    }

#pragma unroll
    for (int mt = 0; mt < 2; mt++) {
        const int r0 = blockIdx.y * TILE + warp_m + mt * 16 + gid;
#pragma unroll
        for (int nt = 0; nt < 8; nt++) {
            const int col = blockIdx.x * TILE + warp_n + nt * 8 + 2 * tig;
            float bx = 0.f, by = 0.f;
            if (HAS_BIAS) { bx = __ldg(bias + col); by = __ldg(bias + col + 1); }
            float2 v0, v1;
            v0.x = acc[mt][nt][0] * alpha + bx;
            v0.y = acc[mt][nt][1] * alpha + by;
            v1.x = acc[mt][nt][2] * alpha + bx;
            v1.y = acc[mt][nt][3] * alpha + by;
            if (OUT_HALF) {
                __half* Cb = (__half*)Cv + batch * strideC;
                *(__half2*)(Cb + (size_t)r0 * ldc + col) = __floats2half2_rn(v0.x, v0.y);
                *(__half2*)(Cb + (size_t)(r0 + 8) * ldc + col) = __floats2half2_rn(v1.x, v1.y);
            } else {
                float* Cb = (float*)Cv + batch * strideC;
                *(float2*)(Cb + (size_t)r0 * ldc + col) = v0;
                *(float2*)(Cb + (size_t)(r0 + 8) * ldc + col) = v1;
            }
        }
    }
}

// ---------------- prep: flat fp32 -> fp16 --------------------------------------
__global__ void k_cvt_h(const float* __restrict__ src, __half* __restrict__ dst) {
    size_t i = (size_t)blockIdx.x * blockDim.x + threadIdx.x;
    float4 v = ((const float4*)src)[i];
    ((__half2*)dst)[i * 2]     = __floats2half2_rn(v.x, v.y);
    ((__half2*)dst)[i * 2 + 1] = __floats2half2_rn(v.z, v.w);
}

// ---------------- softmax pass 1: stats + fp16 weights (critical path) ---------
__global__ void __launch_bounds__(256) softmax_p1(
    const float* __restrict__ attn, const int* __restrict__ mask,
    __half* __restrict__ attn16)
{
    const int row = blockIdx.x;
    const int b = row / Q_;
    const int4* mrow = (const int4*)(mask + (size_t)b * D_);
    const float4* s4 = (const float4*)(attn + (size_t)row * D_);
    __half2* h2 = (__half2*)(attn16 + (size_t)row * D_);
    const int tid = threadIdx.x;

    float v[16];
    float mx = -INFINITY;
#pragma unroll
    for (int i = 0; i < 4; i++) {
        const int c = tid + i * 256;
        int4 m = mrow[c];
        float4 x = s4[c];
        v[i * 4 + 0] = (m.x != 0) ? x.x : -INFINITY;
        v[i * 4 + 1] = (m.y != 0) ? x.y : -INFINITY;
        v[i * 4 + 2] = (m.z != 0) ? x.z : -INFINITY;
        v[i * 4 + 3] = (m.w != 0) ? x.w : -INFINITY;
        mx = fmaxf(mx, fmaxf(fmaxf(v[i * 4], v[i * 4 + 1]), fmaxf(v[i * 4 + 2], v[i * 4 + 3])));
    }

    __shared__ float red[8];
#pragma unroll
    for (int off = 16; off > 0; off >>= 1)
        mx = fmaxf(mx, __shfl_xor_sync(0xffffffffu, mx, off));
    if ((tid & 31) == 0) red[tid >> 5] = mx;
    __syncthreads();
    if (tid < 32) {
        float m2 = (tid < 8) ? red[tid] : -INFINITY;
#pragma unroll
        for (int off = 4; off > 0; off >>= 1)
            m2 = fmaxf(m2, __shfl_xor_sync(0xffffffffu, m2, off));
        if (tid == 0) red[0] = m2;
    }
    __syncthreads();
    mx = red[0];

    float sum = 0.0f;
#pragma unroll
    for (int i = 0; i < 16; i++) {
        float e = (v[i] != -INFINITY) ? expf(v[i] - mx) : 0.0f;
        v[i] = e;
        sum += e;
    }
#pragma unroll
    for (int off = 16; off > 0; off >>= 1)
        sum += __shfl_xor_sync(0xffffffffu, sum, off);
    __syncthreads();
    if ((tid & 31) == 0) red[tid >> 5] = sum;
    __syncthreads();
    if (tid < 32) {
        float s2 = (tid < 8) ? red[tid] : 0.0f;
#pragma unroll
        for (int off = 4; off > 0; off >>= 1)
            s2 += __shfl_xor_sync(0xffffffffu, s2, off);
        if (tid == 0) red[0] = s2;
    }
    __syncthreads();
    const float inv = 1.0f / red[0];

    if (tid == 0) { g_mx[row] = mx; g_inv[row] = inv; }

#pragma unroll
    for (int i = 0; i < 4; i++) {
        const int c = tid + i * 256;
        h2[c * 2]     = __floats2half2_rn(v[i * 4 + 0] * inv, v[i * 4 + 1] * inv);
        h2[c * 2 + 1] = __floats2half2_rn(v[i * 4 + 2] * inv, v[i * 4 + 3] * inv);
    }
}

// ---------------- softmax pass 2: fp32 weights in place (off critical path) ----
__global__ void __launch_bounds__(256) softmax_p2(
    float* __restrict__ attn, const int* __restrict__ mask)
{
    const int row = blockIdx.x;
    const int b = row / Q_;
    const int4* mrow = (const int4*)(mask + (size_t)b * D_);
    float4* s4 = (float4*)(attn + (size_t)row * D_);
    const int tid = threadIdx.x;
    const float mx = g_mx[row];
    const float inv = g_inv[row];

#pragma unroll
    for (int i = 0; i < 4; i++) {
        const int c = tid + i * 256;
        int4 m = mrow[c];
        float4 x = s4[c];
        float4 o;
        o.x = (m.x != 0) ? expf(x.x - mx) * inv : 0.0f;
        o.y = (m.y != 0) ? expf(x.y - mx) * inv : 0.0f;
        o.z = (m.z != 0) ? expf(x.z - mx) * inv : 0.0f;
        o.w = (m.w != 0) ? expf(x.w - mx) * inv : 0.0f;
        s4[c] = o;
    }
}

// ---------------- launch --------------------------------------------------------
extern "C" void kernel_launch(void* const* d_in, const int* in_sizes, int n_in,
                              void* d_out, int out_size)
{
    const float* query = (const float*)d_in[0];   // [B,Q,H]
    const float* doc   = (const float*)d_in[1];   // [B,D,H]
    const int*   mask  = (const int*)d_in[2];     // [B,D]
    const float* W     = (const float*)d_in[3];   // [H,H]
    const float* bias  = (const float*)d_in[4];   // [H]

    float* out = (float*)d_out;
    float* retrieved = out;                               // [B,Q,H]
    float* attn = out + (size_t)B_ * Q_ * H_;             // [B,Q,D]

    __half *p_q16, *p_query16, *p_W16, *p_doc16, *p_attn16;
    cudaGetSymbolAddress((void**)&p_q16, g_q16);
    cudaGetSymbolAddress((void**)&p_query16, g_query16);
    cudaGetSymbolAddress((void**)&p_W16, g_W16);
    cudaGetSymbolAddress((void**)&p_doc16, g_doc16);
    cudaGetSymbolAddress((void**)&p_attn16, g_attn16);

    cudaFuncSetAttribute(wgemm_h<true, true, true>,
                         cudaFuncAttributeMaxDynamicSharedMemorySize, SMEM_BYTES);
    cudaFuncSetAttribute(wgemm_h<false, false, false>,
                         cudaFuncAttributeMaxDynamicSharedMemorySize, SMEM_BYTES);
    cudaFuncSetAttribute(wgemm_h<true, false, false>,
                         cudaFuncAttributeMaxDynamicSharedMemorySize, SMEM_BYTES);

    // side stream + fork/join events (host objects only; intentionally not
    // destroyed — kernel_launch runs only a handful of times)
    cudaStream_t s2;
    cudaStreamCreateWithFlags(&s2, cudaStreamNonBlocking);
    cudaEvent_t eFork, eDoc, eSm, eP2;
    cudaEventCreateWithFlags(&eFork, cudaEventDisableTiming);
    cudaEventCreateWithFlags(&eDoc, cudaEventDisableTiming);
    cudaEventCreateWithFlags(&eSm, cudaEventDisableTiming);
    cudaEventCreateWithFlags(&eP2, cudaEventDisableTiming);

    const float scale = 1.0f / 32.0f;   // 1/sqrt(H)

    // fork: doc -> fp16 on s2, overlapped with query/W prep + GEMM1
    cudaEventRecord(eFork, 0);
    cudaStreamWaitEvent(s2, eFork, 0);
    k_cvt_h<<<((size_t)B_ * D_ * H_) / 4 / 256, 256, 0, s2>>>(doc, p_doc16);
    cudaEventRecord(eDoc, s2);

    // main stream: small preps + GEMM1
    k_cvt_h<<<((size_t)B_ * Q_ * H_) / 4 / 256, 256>>>(query, p_query16);
    k_cvt_h<<<((size_t)H_ * H_) / 4 / 256, 256>>>(W, p_W16);
    {
        dim3 g(H_ / TILE, (B_ * Q_) / TILE, 1);
        wgemm_h<true, true, true><<<g, 256, SMEM_BYTES>>>(
            p_query16, p_W16, p_q16, bias, H_, H_, H_, H_, 1.0f, 0, 0, 0);
    }

    // join doc16, then GEMM2 (scores -> attn fp32)
    cudaStreamWaitEvent(0, eDoc, 0);
    {
        dim3 g(D_ / TILE, Q_ / TILE, B_);
        wgemm_h<false, false, false><<<g, 256, SMEM_BYTES>>>(
            p_q16, p_doc16, attn, nullptr, H_, H_, H_, D_, scale,
            (size_t)Q_ * H_, (size_t)D_ * H_, (size_t)Q_ * D_);
    }

    // softmax pass 1 (fp16 weights + stats) on critical path
    softmax_p1<<<B_ * Q_, 256>>>(attn, mask, p_attn16);

    // fork: fp32 weight write on s2, concurrent with GEMM3
    cudaEventRecord(eSm, 0);
    cudaStreamWaitEvent(s2, eSm, 0);
    softmax_p2<<<B_ * Q_, 256, 0, s2>>>(attn, mask);
    cudaEventRecord(eP2, s2);

    // GEMM3 on main stream
    {
        dim3 g(H_ / TILE, Q_ / TILE, B_);
        wgemm_h<true, false, false><<<g, 256, SMEM_BYTES>>>(
            p_attn16, p_doc16, retrieved, nullptr, D_, D_, H_, H_, 1.0f,
            (size_t)Q_ * D_, (size_t)D_ * H_, (size_t)Q_ * H_);
    }

    // join pass 2 so the graph's end depends on the fp32 output write
    cudaStreamWaitEvent(0, eP2, 0);
}

// round 14
// speedup vs baseline: 1.8749x; 1.0002x over previous
#include <cuda_runtime.h>
#include <cuda_fp16.h>
#include <math.h>
#include <stdint.h>

#define B_  8
#define Q_  512
#define D_  4096
#define H_  1024

#define STAGES  3
#define TILE    128
#define BK      64                         // k halves per stage
#define STRD_H  72                         // K-major smem row stride (halves)
#define STRD_BN 136                        // trans-B smem row stride (halves)
#define A_HALVES (TILE * STRD_H)           // 9216
#define B_REGION 9216                      // >= max(128*72, 64*136=8704)
#define STAGE_HALVES (A_HALVES + B_REGION) // 18432
#define SMEM_BYTES (STAGES * STAGE_HALVES * 2)   // 110592

// ---------------- scratch (static device memory; no allocs allowed) ----------
__device__ __align__(16) __half g_q16[(size_t)B_ * Q_ * H_];     // projected queries
__device__ __align__(16) __half g_query16[(size_t)B_ * Q_ * H_]; // fp16(query)
__device__ __align__(16) __half g_W16[(size_t)H_ * H_];          // fp16(W) [k][n]
__device__ __align__(16) __half g_doc16[(size_t)B_ * D_ * H_];   // fp16(doc) [B,D,H]
__device__ __align__(16) __half g_attn16[(size_t)B_ * Q_ * D_];  // fp16(attn) [B,Q,D]
__device__ float g_mx[B_ * Q_];                                   // softmax row max
__device__ float g_inv[B_ * Q_];                                  // softmax row 1/sum

// ---------------- helpers -----------------------------------------------------
__device__ __forceinline__ void cp_async16(uint32_t dst, const void* src) {
    asm volatile("cp.async.cg.shared.global [%0], [%1], 16;" :: "r"(dst), "l"(src));
}
#define CP_COMMIT() asm volatile("cp.async.commit_group;" ::: "memory")
#define CP_WAIT(n)  asm volatile("cp.async.wait_group %0;" :: "n"(n) : "memory")

__device__ __forceinline__ uint32_t smem_u32(const void* p) {
    uint32_t a;
    asm("{ .reg .u64 t; cvta.to.shared.u64 t, %1; cvt.u32.u64 %0, t; }" : "=r"(a) : "l"(p));
    return a;
}

__device__ __forceinline__ void ldsm_x4(uint32_t* r, uint32_t addr) {
    asm volatile("ldmatrix.sync.aligned.m8n8.x4.shared.b16 {%0,%1,%2,%3}, [%4];"
                 : "=r"(r[0]), "=r"(r[1]), "=r"(r[2]), "=r"(r[3]) : "r"(addr));
}
__device__ __forceinline__ void ldsm_x4_t(uint32_t* r, uint32_t addr) {
    asm volatile("ldmatrix.sync.aligned.m8n8.x4.trans.shared.b16 {%0,%1,%2,%3}, [%4];"
                 : "=r"(r[0]), "=r"(r[1]), "=r"(r[2]), "=r"(r[3]) : "r"(addr));
}

__device__ __forceinline__ void mma_f16(float* c, const uint32_t* a, const uint32_t* b) {
    asm volatile(
        "mma.sync.aligned.m16n8k16.row.col.f32.f16.f16.f32 "
        "{%0,%1,%2,%3}, {%4,%5,%6,%7}, {%8,%9}, {%0,%1,%2,%3};"
        : "+f"(c[0]), "+f"(c[1]), "+f"(c[2]), "+f"(c[3])
        : "r"(a[0]), "r"(a[1]), "r"(a[2]), "r"(a[3]), "r"(b[0]), "r"(b[1]));
}

// ---------------- warp-MMA FP16 GEMM (CTA 128x128, warp 32x64, BK=64) ---------
// Single barrier per K-iteration: the top-of-loop __syncthreads both releases
// the stage consumed last iteration (for overwrite) and orders cp.async data.
template <bool B_TRANS, bool HAS_BIAS, bool OUT_HALF>
__global__ void __launch_bounds__(256, 2) wgemm_h(
    const __half* __restrict__ A, const __half* __restrict__ Bm,
    void* __restrict__ Cv, const float* __restrict__ bias,
    int K, int lda, int ldb, int ldc, float alpha,
    size_t strideA, size_t strideB, size_t strideC)
{
    extern __shared__ __half smh[];
    const uint32_t sbase = smem_u32(smh);

    const int tid  = threadIdx.x;
    const int lane = tid & 31;
    const int wid  = tid >> 5;
    const int gid  = lane >> 2;
    const int tig  = lane & 3;
    const int warp_m = (wid & 3) * 32;
    const int warp_n = (wid >> 2) * 64;

    const size_t batch = blockIdx.z;
    const __half* Ab = A + batch * strideA + (size_t)(blockIdx.y * TILE) * lda;
    const __half* Bb;
    if (B_TRANS)
        Bb = Bm + batch * strideB + blockIdx.x * TILE;
    else
        Bb = Bm + batch * strideB + (size_t)(blockIdx.x * TILE) * ldb;

    const uint32_t offA = ((uint32_t)(warp_m + (lane & 15)) * STRD_H + ((lane >> 4) << 3)) * 2;
    const uint32_t offB = ((uint32_t)(warp_n + ((lane >> 4) << 3) + (lane & 7)) * STRD_H + (lane & 8)) * 2
                          + A_HALVES * 2;
    const uint32_t offBT = ((uint32_t)((lane & 7) + ((lane >> 3) & 1) * 8) * STRD_BN
                            + warp_n + ((lane >> 4) << 3)) * 2
                          + A_HALVES * 2;

    float acc[2][8][4];
#pragma unroll
    for (int mt = 0; mt < 2; mt++)
#pragma unroll
        for (int nt = 0; nt < 8; nt++)
#pragma unroll
            for (int i = 0; i < 4; i++) acc[mt][nt][i] = 0.0f;

    const int NK = K / BK;

    auto load_stage = [&](int kb) {
        const int s = kb % STAGES;
        const uint32_t stA = sbase + s * STAGE_HALVES * 2;
        const uint32_t stB = stA + A_HALVES * 2;
        const __half* gA = Ab + kb * BK;
#pragma unroll
        for (int r = 0; r < 4; r++) {
            const int c = tid + r * 256;
            const int rw = c >> 3, q = (c & 7) * 8;
            cp_async16(stA + (rw * STRD_H + q) * 2, gA + (size_t)rw * lda + q);
        }
        if (B_TRANS) {
            const __half* gB = Bb + (size_t)(kb * BK) * ldb;
#pragma unroll
            for (int r = 0; r < 4; r++) {
                const int c = tid + r * 256;
                const int rw = c >> 4, q = (c & 15) * 8;
                cp_async16(stB + (rw * STRD_BN + q) * 2, gB + (size_t)rw * ldb + q);
            }
        } else {
            const __half* gB = Bb + kb * BK;
#pragma unroll
            for (int r = 0; r < 4; r++) {
                const int c = tid + r * 256;
                const int rw = c >> 3, q = (c & 7) * 8;
                cp_async16(stB + (rw * STRD_H + q) * 2, gB + (size_t)rw * ldb + q);
            }
        }
    };

#pragma unroll
    for (int s = 0; s < STAGES - 1; s++) {
        load_stage(s);
        CP_COMMIT();
    }

    for (int kb = 0; kb < NK; kb++) {
        CP_WAIT(STAGES - 2);
        __syncthreads();          // releases stage (kb-1)%3 AND makes stage kb visible

        const int kn = kb + STAGES - 1;
        if (kn < NK) load_stage(kn);
        CP_COMMIT();

        const uint32_t stOff = sbase + (kb % STAGES) * STAGE_HALVES * 2;
#pragma unroll
        for (int kk = 0; kk < BK; kk += 16) {
            uint32_t a[2][4], b[4][4];
#pragma unroll
            for (int mt = 0; mt < 2; mt++)
                ldsm_x4(a[mt], stOff + offA + (mt * 16 * STRD_H + kk) * 2);
#pragma unroll
            for (int p = 0; p < 4; p++) {
                if (B_TRANS)
                    ldsm_x4_t(b[p], stOff + offBT + (kk * STRD_BN + p * 16) * 2);
                else
                    ldsm_x4(b[p], stOff + offB + (p * 16 * STRD_H + kk) * 2);
            }
#pragma unroll
            for (int mt = 0; mt < 2; mt++)
#pragma unroll
                for (int p = 0; p < 4; p++) {
                    mma_f16(acc[mt][2 * p],     a[mt], &b[p][0]);
                    mma_f16(acc[mt][2 * p + 1], a[mt], &b[p][2]);
                }
        }
        // no trailing barrier: next iteration's top barrier provides the
        // consume-before-overwrite guarantee for this stage
    }

#pragma unroll
    for (int mt = 0; mt < 2; mt++) {
        const int r0 = blockIdx.y * TILE + warp_m + mt * 16 + gid;
#pragma unroll
        for (int nt = 0; nt < 8; nt++) {
            const int col = blockIdx.x * TILE + warp_n + nt * 8 + 2 * tig;
            float bx = 0.f, by = 0.f;
            if (HAS_BIAS) { bx = __ldg(bias + col); by = __ldg(bias + col + 1); }
            float2 v0, v1;
            v0.x = acc[mt][nt][0] * alpha + bx;
            v0.y = acc[mt][nt][1] * alpha + by;
            v1.x = acc[mt][nt][2] * alpha + bx;
            v1.y = acc[mt][nt][3] * alpha + by;
            if (OUT_HALF) {
                __half* Cb = (__half*)Cv + batch * strideC;
                *(__half2*)(Cb + (size_t)r0 * ldc + col) = __floats2half2_rn(v0.x, v0.y);
                *(__half2*)(Cb + (size_t)(r0 + 8) * ldc + col) = __floats2half2_rn(v1.x, v1.y);
            } else {
                float* Cb = (float*)Cv + batch * strideC;
                *(float2*)(Cb + (size_t)r0 * ldc + col) = v0;
                *(float2*)(Cb + (size_t)(r0 + 8) * ldc + col) = v1;
            }
        }
    }
}

// ---------------- prep: flat fp32 -> fp16 --------------------------------------
__global__ void k_cvt_h(const float* __restrict__ src, __half* __restrict__ dst) {
    size_t i = (size_t)blockIdx.x * blockDim.x + threadIdx.x;
    float4 v = ((const float4*)src)[i];
    ((__half2*)dst)[i * 2]     = __floats2half2_rn(v.x, v.y);
    ((__half2*)dst)[i * 2 + 1] = __floats2half2_rn(v.z, v.w);
}

// ---------------- softmax pass 1: stats + fp16 weights (critical path) ---------
__global__ void __launch_bounds__(256) softmax_p1(
    const float* __restrict__ attn, const int* __restrict__ mask,
    __half* __restrict__ attn16)
{
    const int row = blockIdx.x;
    const int b = row / Q_;
    const int4* mrow = (const int4*)(mask + (size_t)b * D_);
    const float4* s4 = (const float4*)(attn + (size_t)row * D_);
    __half2* h2 = (__half2*)(attn16 + (size_t)row * D_);
    const int tid = threadIdx.x;

    float v[16];
    float mx = -INFINITY;
#pragma unroll
    for (int i = 0; i < 4; i++) {
        const int c = tid + i * 256;
        int4 m = mrow[c];
        float4 x = s4[c];
        v[i * 4 + 0] = (m.x != 0) ? x.x : -INFINITY;
        v[i * 4 + 1] = (m.y != 0) ? x.y : -INFINITY;
        v[i * 4 + 2] = (m.z != 0) ? x.z : -INFINITY;
        v[i * 4 + 3] = (m.w != 0) ? x.w : -INFINITY;
        mx = fmaxf(mx, fmaxf(fmaxf(v[i * 4], v[i * 4 + 1]), fmaxf(v[i * 4 + 2], v[i * 4 + 3])));
    }

    __shared__ float red[8];
#pragma unroll
    for (int off = 16; off > 0; off >>= 1)
        mx = fmaxf(mx, __shfl_xor_sync(0xffffffffu, mx, off));
    if ((tid & 31) == 0) red[tid >> 5] = mx;
    __syncthreads();
    if (tid < 32) {
        float m2 = (tid < 8) ? red[tid] : -INFINITY;
#pragma unroll
        for (int off = 4; off > 0; off >>= 1)
            m2 = fmaxf(m2, __shfl_xor_sync(0xffffffffu, m2, off));
        if (tid == 0) red[0] = m2;
    }
    __syncthreads();
    mx = red[0];

    float sum = 0.0f;
#pragma unroll
    for (int i = 0; i < 16; i++) {
        float e = (v[i] != -INFINITY) ? expf(v[i] - mx) : 0.0f;
        v[i] = e;
        sum += e;
    }
#pragma unroll
    for (int off = 16; off > 0; off >>= 1)
        sum += __shfl_xor_sync(0xffffffffu, sum, off);
    __syncthreads();
    if ((tid & 31) == 0) red[tid >> 5] = sum;
    __syncthreads();
    if (tid < 32) {
        float s2 = (tid < 8) ? red[tid] : 0.0f;
#pragma unroll
        for (int off = 4; off > 0; off >>= 1)
            s2 += __shfl_xor_sync(0xffffffffu, s2, off);
        if (tid == 0) red[0] = s2;
    }
    __syncthreads();
    const float inv = 1.0f / red[0];

    if (tid == 0) { g_mx[row] = mx; g_inv[row] = inv; }

#pragma unroll
    for (int i = 0; i < 4; i++) {
        const int c = tid + i * 256;
        h2[c * 2]     = __floats2half2_rn(v[i * 4 + 0] * inv, v[i * 4 + 1] * inv);
        h2[c * 2 + 1] = __floats2half2_rn(v[i * 4 + 2] * inv, v[i * 4 + 3] * inv);
    }
}

// ---------------- softmax pass 2: fp32 weights in place (off critical path) ----
__global__ void __launch_bounds__(256) softmax_p2(
    float* __restrict__ attn, const int* __restrict__ mask)
{
    const int row = blockIdx.x;
    const int b = row / Q_;
    const int4* mrow = (const int4*)(mask + (size_t)b * D_);
    float4* s4 = (float4*)(attn + (size_t)row * D_);
    const int tid = threadIdx.x;
    const float mx = g_mx[row];
    const float inv = g_inv[row];

#pragma unroll
    for (int i = 0; i < 4; i++) {
        const int c = tid + i * 256;
        int4 m = mrow[c];
        float4 x = s4[c];
        float4 o;
        o.x = (m.x != 0) ? expf(x.x - mx) * inv : 0.0f;
        o.y = (m.y != 0) ? expf(x.y - mx) * inv : 0.0f;
        o.z = (m.z != 0) ? expf(x.z - mx) * inv : 0.0f;
        o.w = (m.w != 0) ? expf(x.w - mx) * inv : 0.0f;
        s4[c] = o;
    }
}

// ---------------- launch --------------------------------------------------------
extern "C" void kernel_launch(void* const* d_in, const int* in_sizes, int n_in,
                              void* d_out, int out_size)
{
    const float* query = (const float*)d_in[0];   // [B,Q,H]
    const float* doc   = (const float*)d_in[1];   // [B,D,H]
    const int*   mask  = (const int*)d_in[2];     // [B,D]
    const float* W     = (const float*)d_in[3];   // [H,H]
    const float* bias  = (const float*)d_in[4];   // [H]

    float* out = (float*)d_out;
    float* retrieved = out;                               // [B,Q,H]
    float* attn = out + (size_t)B_ * Q_ * H_;             // [B,Q,D]

    __half *p_q16, *p_query16, *p_W16, *p_doc16, *p_attn16;
    cudaGetSymbolAddress((void**)&p_q16, g_q16);
    cudaGetSymbolAddress((void**)&p_query16, g_query16);
    cudaGetSymbolAddress((void**)&p_W16, g_W16);
    cudaGetSymbolAddress((void**)&p_doc16, g_doc16);
    cudaGetSymbolAddress((void**)&p_attn16, g_attn16);

    cudaFuncSetAttribute(wgemm_h<true, true, true>,
                         cudaFuncAttributeMaxDynamicSharedMemorySize, SMEM_BYTES);
    cudaFuncSetAttribute(wgemm_h<false, false, false>,
                         cudaFuncAttributeMaxDynamicSharedMemorySize, SMEM_BYTES);
    cudaFuncSetAttribute(wgemm_h<true, false, false>,
                         cudaFuncAttributeMaxDynamicSharedMemorySize, SMEM_BYTES);

    cudaStream_t s2;
    cudaStreamCreateWithFlags(&s2, cudaStreamNonBlocking);
    cudaEvent_t eFork, eDoc, eSm, eP2;
    cudaEventCreateWithFlags(&eFork, cudaEventDisableTiming);
    cudaEventCreateWithFlags(&eDoc, cudaEventDisableTiming);
    cudaEventCreateWithFlags(&eSm, cudaEventDisableTiming);
    cudaEventCreateWithFlags(&eP2, cudaEventDisableTiming);

    const float scale = 1.0f / 32.0f;   // 1/sqrt(H)

    // fork: doc -> fp16 on s2, overlapped with query/W prep + GEMM1
    cudaEventRecord(eFork, 0);
    cudaStreamWaitEvent(s2, eFork, 0);
    k_cvt_h<<<((size_t)B_ * D_ * H_) / 4 / 256, 256, 0, s2>>>(doc, p_doc16);
    cudaEventRecord(eDoc, s2);

    k_cvt_h<<<((size_t)B_ * Q_ * H_) / 4 / 256, 256>>>(query, p_query16);
    k_cvt_h<<<((size_t)H_ * H_) / 4 / 256, 256>>>(W, p_W16);
    {
        dim3 g(H_ / TILE, (B_ * Q_) / TILE, 1);
        wgemm_h<true, true, true><<<g, 256, SMEM_BYTES>>>(
            p_query16, p_W16, p_q16, bias, H_, H_, H_, H_, 1.0f, 0, 0, 0);
    }

    cudaStreamWaitEvent(0, eDoc, 0);
    {
        dim3 g(D_ / TILE, Q_ / TILE, B_);
        wgemm_h<false, false, false><<<g, 256, SMEM_BYTES>>>(
            p_q16, p_doc16, attn, nullptr, H_, H_, H_, D_, scale,
            (size_t)Q_ * H_, (size_t)D_ * H_, (size_t)Q_ * D_);
    }

    softmax_p1<<<B_ * Q_, 256>>>(attn, mask, p_attn16);

    cudaEventRecord(eSm, 0);
    cudaStreamWaitEvent(s2, eSm, 0);
    softmax_p2<<<B_ * Q_, 256, 0, s2>>>(attn, mask);
    cudaEventRecord(eP2, s2);

    {
        dim3 g(H_ / TILE, Q_ / TILE, B_);
        wgemm_h<true, false, false><<<g, 256, SMEM_BYTES>>>(
            p_attn16, p_doc16, retrieved, nullptr, D_, D_, H_, H_, 1.0f,
            (size_t)Q_ * D_, (size_t)D_ * H_, (size_t)Q_ * H_);
    }

    cudaStreamWaitEvent(0, eP2, 0);
}